// round 10
// baseline (speedup 1.0000x reference)
#include <cuda_runtime.h>
#include <cstdint>

#define Bc   4
#define Nn   1024
#define Ee   1024
#define BHn  64
#define Mtot 4096   // B*N

// Projected Q/K hi/lo bf16x2 planes, PAIR-INTERLEAVED within each 8-block:
// original pair j of block b stored at b*8 + (j&3)*2 + (j>>2).
__device__ uint32_t g_qh[Mtot * 512];
__device__ uint32_t g_ql[Mtot * 512];
__device__ uint32_t g_kh[Mtot * 512];
__device__ uint32_t g_kl[Mtot * 512];
__device__ float    g_v [Mtot * Ee];
// V^T packed planes [bh][d][cpair], same interleave on cpair.
__device__ uint32_t g_vth[64 * 64 * 512];
__device__ uint32_t g_vtl[64 * 64 * 512];
// Packed GEMM input planes (NOT interleaved; proj reads scalar).
__device__ uint32_t g_pxh[3][Mtot * 512];
__device__ uint32_t g_pxl[3][Mtot * 512];
__device__ uint32_t g_pwh[3][1024 * 512];
__device__ uint32_t g_pwl[3][1024 * 512];
// Fallback weights buffer if the harness output only holds attn.
__device__ float g_w[(size_t)BHn * Nn * Nn];

// ===========================================================================
// helpers
// ===========================================================================
static __device__ __forceinline__ uint32_t smem_u32(const void* p) {
    uint32_t a;
    asm("{ .reg .u64 t; cvta.to.shared.u64 t, %1; cvt.u32.u64 %0, t; }" : "=r"(a) : "l"(p));
    return a;
}
static __device__ __forceinline__ uint32_t pack_bf16(float x0, float x1) {
    uint32_t r;
    asm("cvt.rn.bf16x2.f32 %0, %1, %2;" : "=r"(r) : "f"(x1), "f"(x0));
    return r;
}
static __device__ __forceinline__ void split2(float x0, float x1, uint32_t& h, uint32_t& l) {
    h = pack_bf16(x0, x1);
    float h0 = __uint_as_float(h << 16);
    float h1 = __uint_as_float(h & 0xFFFF0000u);
    l = pack_bf16(x0 - h0, x1 - h1);
}
static __device__ __forceinline__ void mma_bf16(float* c, const uint32_t* a, const uint32_t* b) {
    asm volatile(
        "mma.sync.aligned.m16n8k16.row.col.f32.bf16.bf16.f32 "
        "{%0,%1,%2,%3}, {%4,%5,%6,%7}, {%8,%9}, {%0,%1,%2,%3};"
        : "+f"(c[0]), "+f"(c[1]), "+f"(c[2]), "+f"(c[3])
        : "r"(a[0]), "r"(a[1]), "r"(a[2]), "r"(a[3]), "r"(b[0]), "r"(b[1]));
}
static __device__ __forceinline__ void cp16(uint32_t dst, const void* src) {
    asm volatile("cp.async.cg.shared.global [%0], [%1], 16;" :: "r"(dst), "l"(src));
}
static __device__ __forceinline__ void cp_commit() {
    asm volatile("cp.async.commit_group;" ::: "memory");
}
template<int N> static __device__ __forceinline__ void cp_wait() {
    asm volatile("cp.async.wait_group %0;" :: "n"(N) : "memory");
}

// ===========================================================================
// Pack kernel: fp32 -> separate hi/lo plane pairs for proj inputs.
// ===========================================================================
__global__ __launch_bounds__(256) void pack_kernel(
    const float* __restrict__ xq, const float* __restrict__ xk, const float* __restrict__ xv,
    const float* __restrict__ wq, const float* __restrict__ wk, const float* __restrict__ wv)
{
    const int z = blockIdx.y;
    const float* src; uint32_t* dh; uint32_t* dl; int nf4;
    switch (z) {
        case 0: src = xq; dh = g_pxh[0]; dl = g_pxl[0]; nf4 = Mtot * 256; break;
        case 1: src = xk; dh = g_pxh[1]; dl = g_pxl[1]; nf4 = Mtot * 256; break;
        case 2: src = xv; dh = g_pxh[2]; dl = g_pxl[2]; nf4 = Mtot * 256; break;
        case 3: src = wq; dh = g_pwh[0]; dl = g_pwl[0]; nf4 = 1024 * 256; break;
        case 4: src = wk; dh = g_pwh[1]; dl = g_pwl[1]; nf4 = 1024 * 256; break;
        default: src = wv; dh = g_pwh[2]; dl = g_pwl[2]; nf4 = 1024 * 256; break;
    }
    int i = blockIdx.x * 256 + threadIdx.x;
    if (i >= nf4) return;
    float4 v = *(const float4*)(src + (size_t)i * 4);
    uint32_t h0, l0, h1, l1;
    split2(v.x, v.y, h0, l0);
    split2(v.z, v.w, h1, l1);
    *(uint2*)&dh[2 * i] = make_uint2(h0, h1);
    *(uint2*)&dl[2 * i] = make_uint2(l0, l1);
}

// ===========================================================================
// Projection GEMM: C = X @ W^T + b, cp.async double-buffered, 2 CTAs/SM.
// ===========================================================================
#define PSP 20
#define PSTAGE (4 * 128 * PSP)                      // 10240 words
#define PROJ_SMEM_BYTES ((2 * PSTAGE + 128) * 4)    // 82432

__global__ __launch_bounds__(256, 2) void proj_mma_kernel(
    const float* __restrict__ bq, const float* __restrict__ bk, const float* __restrict__ bv)
{
    extern __shared__ uint32_t psm[];
    float* bsm = (float*)(psm + 2 * PSTAGE);
    const uint32_t smb = smem_u32(psm);

    const int z = blockIdx.z;
    const uint32_t* xh = g_pxh[z]; const uint32_t* xl = g_pxl[z];
    const uint32_t* wh = g_pwh[z]; const uint32_t* wl = g_pwl[z];
    const float* bias = (z == 0) ? bq : (z == 1) ? bk : bv;

    const int tid = threadIdx.x;
    const int w = tid >> 5, lane = tid & 31;
    const int g = lane >> 2, t = lane & 3;
    const int bm = blockIdx.x * 128, bn = blockIdx.y * 128;
    const int wm = w >> 2, wn = w & 3;

    if (tid < 128) bsm[tid] = bias[bn + tid];

    auto issueP = [&](int kc) {
        int st = kc & 1;
        #pragma unroll
        for (int s = 0; s < 8; s++) {
            int idx = tid + 256 * s;          // 0..2047
            int plane = idx >> 9;
            int row = (idx >> 2) & 127;
            int seg = idx & 3;
            const uint32_t* src;
            if (plane == 0)      src = xh + (size_t)(bm + row) * 512 + kc * 16 + seg * 4;
            else if (plane == 1) src = xl + (size_t)(bm + row) * 512 + kc * 16 + seg * 4;
            else if (plane == 2) src = wh + (size_t)(bn + row) * 512 + kc * 16 + seg * 4;
            else                 src = wl + (size_t)(bn + row) * 512 + kc * 16 + seg * 4;
            cp16(smb + (uint32_t)(st * PSTAGE + plane * 128 * PSP + row * PSP + seg * 4) * 4, src);
        }
        cp_commit();
    };

    issueP(0);
    issueP(1);

    float acc[4][4][4];
    #pragma unroll
    for (int i = 0; i < 4; i++)
        #pragma unroll
        for (int j = 0; j < 4; j++)
            #pragma unroll
            for (int k = 0; k < 4; k++) acc[i][j][k] = 0.0f;

    #pragma unroll 1
    for (int kc = 0; kc < 32; kc++) {
        if (kc == 31) cp_wait<0>(); else cp_wait<1>();
        __syncthreads();
        const uint32_t* XH = psm + (kc & 1) * PSTAGE;
        const uint32_t* XL = XH + 128 * PSP;
        const uint32_t* WH = XH + 2 * 128 * PSP;
        const uint32_t* WL = XH + 3 * 128 * PSP;

        #pragma unroll
        for (int ks = 0; ks < 2; ks++) {
            uint32_t bhf[4][2], blf[4][2];
            #pragma unroll
            for (int nt = 0; nt < 4; nt++) {
                int rb = (wn * 32 + nt * 8 + g) * PSP + ks * 8 + t;
                bhf[nt][0] = WH[rb]; bhf[nt][1] = WH[rb + 4];
                blf[nt][0] = WL[rb]; blf[nt][1] = WL[rb + 4];
            }
            #pragma unroll
            for (int mt = 0; mt < 4; mt++) {
                int ra = (wm * 64 + mt * 16 + g) * PSP + ks * 8 + t;
                uint32_t ah[4] = {XH[ra], XH[ra + 8 * PSP], XH[ra + 4], XH[ra + 8 * PSP + 4]};
                uint32_t al[4] = {XL[ra], XL[ra + 8 * PSP], XL[ra + 4], XL[ra + 8 * PSP + 4]};
                #pragma unroll
                for (int nt = 0; nt < 4; nt++) {
                    mma_bf16(acc[mt][nt], ah, bhf[nt]);
                    mma_bf16(acc[mt][nt], ah, blf[nt]);
                    mma_bf16(acc[mt][nt], al, bhf[nt]);
                }
            }
        }
        __syncthreads();
        if (kc < 30) issueP(kc + 2);
    }

    #pragma unroll
    for (int mt = 0; mt < 4; mt++) {
        int row = wm * 64 + mt * 16 + g;
        #pragma unroll
        for (int nt = 0; nt < 4; nt++) {
            int col = wn * 32 + nt * 8 + 2 * t;
            float bx = bsm[col], by = bsm[col + 1];
            float c00 = acc[mt][nt][0] + bx, c01 = acc[mt][nt][1] + by;
            float c10 = acc[mt][nt][2] + bx, c11 = acc[mt][nt][3] + by;
            if (z < 2) {
                uint32_t* dh = (z == 0) ? g_qh : g_kh;
                uint32_t* dl = (z == 0) ? g_ql : g_kl;
                // interleaved pair index: p' = blk*8 + 2t + (nt&1)
                int pl = (wn * 2 + (nt >> 1)) * 8 + 2 * t + (nt & 1);
                size_t p0 = (size_t)(bm + row) * 512 + (bn >> 1) + pl;
                size_t p1 = (size_t)(bm + row + 8) * 512 + (bn >> 1) + pl;
                uint32_t h, l;
                split2(c00, c01, h, l);
                dh[p0] = h; dl[p0] = l;
                split2(c10, c11, h, l);
                dh[p1] = h; dl[p1] = l;
            } else {
                *(float2*)(g_v + (size_t)(bm + row) * 1024 + bn + col) = make_float2(c00, c01);
                *(float2*)(g_v + (size_t)(bm + row + 8) * 1024 + bn + col) = make_float2(c10, c11);
            }
        }
    }
}

// ===========================================================================
// V transpose+pack: g_v (natural) -> g_vth/g_vtl [bh][d][cpair'] interleaved.
// ===========================================================================
__global__ __launch_bounds__(256) void vt_kernel()
{
    __shared__ uint32_t sh[64 * 65], sl[64 * 65];
    const int bh = blockIdx.y, ct = blockIdx.x, tid = threadIdx.x;

    #pragma unroll
    for (int s = 0; s < 16; s++) {
        int idx = tid + 256 * s;
        int d = idx & 63, cp = idx >> 6;
        const float* p = g_v + (size_t)(ct * 128 + 2 * cp) * 4096 + bh * 64 + d;
        float x0 = p[0], x1 = p[4096];
        uint32_t h, l;
        split2(x0, x1, h, l);
        sh[cp * 65 + d] = h;
        sl[cp * 65 + d] = l;
    }
    __syncthreads();
    #pragma unroll
    for (int s = 0; s < 16; s++) {
        int idx = tid + 256 * s;
        int cp = idx & 63, d = idx >> 6;
        int j = cp & 7;
        int cpi = (cp & ~7) + (j & 3) * 2 + (j >> 2);   // interleave
        size_t o = ((size_t)(bh * 64 + d) << 9) + ct * 64 + cpi;
        g_vth[o] = sh[cp * 65 + d];
        g_vtl[o] = sl[cp * 65 + d];
    }
}

// ===========================================================================
// Attention: register-resident scores, LDS.64 fragments via interleave.
// K rows: 40 words (32 pairs + 8 pad). V rows: 72 words (64 pairs + 8 pad).
// ===========================================================================
#define KV_W    0
#define KVBUFW  10240                   // per-buffer region (K: 2x128x40; V: 2x64x72 fits)
#define QH_W    (2 * KVBUFW)            // 20480
#define QL_W    (QH_W + 1280)
#define SCRM_W  (QL_W + 1280)           // 23040
#define SCRS_W  (SCRM_W + 256)
#define ATTN_SMEM_WORDS (SCRS_W + 256)  // 23552
#define ATTN_SMEM_BYTES (ATTN_SMEM_WORDS * 4)   // 94208

__global__ __launch_bounds__(512, 1) void attn_mma_kernel(
    const float* __restrict__ bias, float* __restrict__ out_attn, float* __restrict__ w_out)
{
    extern __shared__ float sm[];
    uint32_t* KV = (uint32_t*)sm + KV_W;
    uint32_t* QH = (uint32_t*)sm + QH_W;
    uint32_t* QL = (uint32_t*)sm + QL_W;
    float* scrM = sm + SCRM_W;
    float* scrS = sm + SCRS_W;
    const uint32_t smb = smem_u32(sm);

    const int tid = threadIdx.x;
    const int w = tid >> 5, lane = tid & 31;
    const int g = lane >> 2, t = lane & 3;
    const int wm = w >> 3, wn = w & 7;
    const int m0 = wm * 16, n0 = wn * 16;
    const int bh = blockIdx.y;
    const int r0 = blockIdx.x * 32;

    const float* bsrc = bias + (size_t)(bh & 3) * Nn * Nn;
    float* wbase = (w_out != nullptr) ? w_out : g_w;
    float* wrow_base = wbase + (size_t)bh * Nn * Nn;

    auto issueK = [&](int it) {
        int b = it & 1;
        #pragma unroll
        for (int s = 0; s < 4; s++) {
            int idx = tid + 512 * s;
            int plane = idx >> 10;
            int row = (idx >> 3) & 127;
            int seg = idx & 7;
            const uint32_t* src = (plane ? g_kl : g_kh) +
                (size_t)(it * 128 + row) * 2048 + bh * 32 + seg * 4;
            cp16(smb + (uint32_t)(KV_W + b * KVBUFW + plane * 5120 + row * 40 + seg * 4) * 4, src);
        }
        cp_commit();
    };
    auto issueV = [&](int it) {
        int b = it & 1;
        #pragma unroll
        for (int s = 0; s < 4; s++) {
            int idx = tid + 512 * s;
            int plane = idx >> 10;
            int row = (idx >> 4) & 63;
            int seg = idx & 15;
            const uint32_t* src = (plane ? g_vtl : g_vth) +
                (((size_t)(bh * 64 + row)) << 9) + it * 64 + seg * 4;
            cp16(smb + (uint32_t)(KV_W + b * KVBUFW + plane * 4608 + row * 72 + seg * 4) * 4, src);
        }
        cp_commit();
    };

    // ---- prologue: Q, K0, K1 ----
    {
        int plane = tid >> 8, ci = tid & 255, row = ci >> 3, seg = ci & 7;
        const uint32_t* src = (plane ? g_ql : g_qh) +
            (size_t)(r0 + row) * 2048 + bh * 32 + seg * 4;
        cp16(smb + (uint32_t)((plane ? QL_W : QH_W) + row * 40 + seg * 4) * 4, src);
        cp_commit();
    }
    issueK(0);
    issueK(1);

    cp_wait<2>();
    __syncthreads();
    uint32_t qah[4][4], qal[4][4];
    #pragma unroll
    for (int ks = 0; ks < 4; ks++) {
        int ra0 = (m0 + g) * 40 + ks * 8 + 2 * t;
        int ra1 = ra0 + 8 * 40;
        uint2 h0 = *(const uint2*)&QH[ra0];
        uint2 h1 = *(const uint2*)&QH[ra1];
        uint2 l0 = *(const uint2*)&QL[ra0];
        uint2 l1 = *(const uint2*)&QL[ra1];
        qah[ks][0] = h0.x; qah[ks][1] = h1.x; qah[ks][2] = h0.y; qah[ks][3] = h1.y;
        qal[ks][0] = l0.x; qal[ks][1] = l1.x; qal[ks][2] = l0.y; qal[ks][3] = l1.y;
    }

    // ---- scores into registers (64 floats/thread) ----
    float sv[64];
    #pragma unroll
    for (int j = 0; j < 64; j++) sv[j] = 0.0f;

    const int rowg = r0 + m0 + g;

    #pragma unroll
    for (int it = 0; it < 8; it++) {
        if (it == 7) cp_wait<0>(); else cp_wait<1>();
        __syncthreads();
        const uint32_t* KHb = KV + (it & 1) * KVBUFW;
        const uint32_t* KLb = KHb + 5120;
        float* s = sv + it * 8;

        #pragma unroll
        for (int ks = 0; ks < 4; ks++) {
            int rb0 = (n0 + g) * 40 + ks * 8 + 2 * t;
            int rb1 = rb0 + 8 * 40;
            uint2 vh0 = *(const uint2*)&KHb[rb0];
            uint2 vl0 = *(const uint2*)&KLb[rb0];
            uint2 vh1 = *(const uint2*)&KHb[rb1];
            uint2 vl1 = *(const uint2*)&KLb[rb1];
            uint32_t bh0[2] = {vh0.x, vh0.y};
            uint32_t bl0[2] = {vl0.x, vl0.y};
            uint32_t bh1[2] = {vh1.x, vh1.y};
            uint32_t bl1[2] = {vl1.x, vl1.y};
            mma_bf16(s,     qah[ks], bh0);
            mma_bf16(s,     qah[ks], bl0);
            mma_bf16(s,     qal[ks], bh0);
            mma_bf16(s + 4, qah[ks], bh1);
            mma_bf16(s + 4, qah[ks], bl1);
            mma_bf16(s + 4, qal[ks], bh1);
        }
        {
            int c0 = it * 128 + n0 + 2 * t;
            int c1 = c0 + 8;
            float2 b00 = *(const float2*)(bsrc + (size_t)rowg * 1024 + c0);
            float2 b01 = *(const float2*)(bsrc + (size_t)(rowg + 8) * 1024 + c0);
            float2 b10 = *(const float2*)(bsrc + (size_t)rowg * 1024 + c1);
            float2 b11 = *(const float2*)(bsrc + (size_t)(rowg + 8) * 1024 + c1);
            s[0] += b00.x; s[1] += b00.y;
            s[2] += b01.x; s[3] += b01.y;
            s[4] += b10.x; s[5] += b10.y;
            s[6] += b11.x; s[7] += b11.y;
        }
        __syncthreads();
        if (it < 6) issueK(it + 2);
    }

    // ---- V pipeline prologue (overlaps softmax) ----
    issueV(0);
    issueV(1);

    // ---- softmax: quad shuffle + cross-warp smem reduce ----
    float mg = -3.0e38f, mg8 = -3.0e38f;
    #pragma unroll
    for (int it = 0; it < 8; it++) {
        float* s = sv + it * 8;
        mg  = fmaxf(mg,  fmaxf(fmaxf(s[0], s[1]), fmaxf(s[4], s[5])));
        mg8 = fmaxf(mg8, fmaxf(fmaxf(s[2], s[3]), fmaxf(s[6], s[7])));
    }
    mg  = fmaxf(mg,  __shfl_xor_sync(0xffffffffu, mg, 1));
    mg  = fmaxf(mg,  __shfl_xor_sync(0xffffffffu, mg, 2));
    mg8 = fmaxf(mg8, __shfl_xor_sync(0xffffffffu, mg8, 1));
    mg8 = fmaxf(mg8, __shfl_xor_sync(0xffffffffu, mg8, 2));
    if (t == 0) {
        scrM[(m0 + g) * 8 + wn]     = mg;
        scrM[(m0 + g + 8) * 8 + wn] = mg8;
    }
    __syncthreads();
    float Mg = -3.0e38f, Mg8 = -3.0e38f;
    #pragma unroll
    for (int k = 0; k < 8; k++) {
        Mg  = fmaxf(Mg,  scrM[(m0 + g) * 8 + k]);
        Mg8 = fmaxf(Mg8, scrM[(m0 + g + 8) * 8 + k]);
    }
    float sg = 0.0f, sg8 = 0.0f;
    #pragma unroll
    for (int it = 0; it < 8; it++) {
        float* s = sv + it * 8;
        s[0] = __expf(s[0] - Mg);  s[1] = __expf(s[1] - Mg);
        s[4] = __expf(s[4] - Mg);  s[5] = __expf(s[5] - Mg);
        s[2] = __expf(s[2] - Mg8); s[3] = __expf(s[3] - Mg8);
        s[6] = __expf(s[6] - Mg8); s[7] = __expf(s[7] - Mg8);
        sg  += s[0] + s[1] + s[4] + s[5];
        sg8 += s[2] + s[3] + s[6] + s[7];
    }
    sg  += __shfl_xor_sync(0xffffffffu, sg, 1);
    sg  += __shfl_xor_sync(0xffffffffu, sg, 2);
    sg8 += __shfl_xor_sync(0xffffffffu, sg8, 1);
    sg8 += __shfl_xor_sync(0xffffffffu, sg8, 2);
    if (t == 0) {
        scrS[(m0 + g) * 8 + wn]     = sg;
        scrS[(m0 + g + 8) * 8 + wn] = sg8;
    }
    __syncthreads();
    float Sg = 0.0f, Sg8 = 0.0f;
    #pragma unroll
    for (int k = 0; k < 8; k++) {
        Sg  += scrS[(m0 + g) * 8 + k];
        Sg8 += scrS[(m0 + g + 8) * 8 + k];
    }
    const float invg = 1.0f / Sg, invg8 = 1.0f / Sg8;

    // ---- AV loop: per-tile P scale + weights-store + pack + MMA ----
    float* wr0 = wrow_base + (size_t)rowg * 1024;
    float* wr8 = wrow_base + (size_t)(rowg + 8) * 1024;

    float oacc[8][4];
    #pragma unroll
    for (int i = 0; i < 8; i++)
        #pragma unroll
        for (int j = 0; j < 4; j++) oacc[i][j] = 0.0f;

    #pragma unroll
    for (int it = 0; it < 8; it++) {
        if (it == 7) cp_wait<0>(); else cp_wait<1>();
        __syncthreads();
        const uint32_t* VHb = KV + (it & 1) * KVBUFW;
        const uint32_t* VLb = VHb + 4608;

        float* s = sv + it * 8;
        float p0 = s[0] * invg,  p1 = s[1] * invg;
        float p2 = s[2] * invg8, p3 = s[3] * invg8;
        float p4 = s[4] * invg,  p5 = s[5] * invg;
        float p6 = s[6] * invg8, p7 = s[7] * invg8;
        int c0 = it * 128 + n0 + 2 * t;
        *(float2*)&wr0[c0]     = make_float2(p0, p1);
        *(float2*)&wr8[c0]     = make_float2(p2, p3);
        *(float2*)&wr0[c0 + 8] = make_float2(p4, p5);
        *(float2*)&wr8[c0 + 8] = make_float2(p6, p7);
        uint32_t pah[4], pal[4];
        split2(p0, p1, pah[0], pal[0]);
        split2(p2, p3, pah[1], pal[1]);
        split2(p4, p5, pah[2], pal[2]);
        split2(p6, p7, pah[3], pal[3]);

        #pragma unroll
        for (int nt = 0; nt < 8; nt++) {
            int rb = (nt * 8 + g) * 72 + wn * 8 + 2 * t;
            uint2 vh = *(const uint2*)&VHb[rb];
            uint2 vl = *(const uint2*)&VLb[rb];
            uint32_t bh2[2] = {vh.x, vh.y};
            uint32_t bl2[2] = {vl.x, vl.y};
            mma_bf16(oacc[nt], pah, bh2);
            mma_bf16(oacc[nt], pah, bl2);
            mma_bf16(oacc[nt], pal, bh2);
        }
        __syncthreads();
        if (it < 6) issueV(it + 2);
    }

    // ---- tree-reduce 8 wn-partials (overlay on KV region) ----
    __syncthreads();
    float* red = sm + KV_W;
    auto stPart = [&](int b) {
        int base = b * 2176 + wm * 1088;
        #pragma unroll
        for (int nt = 0; nt < 8; nt++) {
            *(float2*)&red[base + g * 66 + nt * 8 + 2 * t] =
                make_float2(oacc[nt][0], oacc[nt][1]);
            *(float2*)&red[base + (g + 8) * 66 + nt * 8 + 2 * t] =
                make_float2(oacc[nt][2], oacc[nt][3]);
        }
    };
    auto addPart = [&](int b) {
        int base = b * 2176 + wm * 1088;
        #pragma unroll
        for (int nt = 0; nt < 8; nt++) {
            float2 p0 = *(float2*)&red[base + g * 66 + nt * 8 + 2 * t];
            float2 p1 = *(float2*)&red[base + (g + 8) * 66 + nt * 8 + 2 * t];
            oacc[nt][0] += p0.x; oacc[nt][1] += p0.y;
            oacc[nt][2] += p1.x; oacc[nt][3] += p1.y;
        }
    };
    if (wn >= 4) stPart(wn - 4);
    __syncthreads();
    if (wn < 4) addPart(wn);
    __syncthreads();
    if (wn == 2 || wn == 3) stPart(wn - 2);
    __syncthreads();
    if (wn < 2) addPart(wn);
    __syncthreads();
    if (wn == 1) stPart(0);
    __syncthreads();
    if (wn == 0) {
        addPart(0);
        size_t ob = (size_t)(bh >> 4) * Nn * Ee + (size_t)(bh & 15) * 64;
        #pragma unroll
        for (int nt = 0; nt < 8; nt++) {
            int col = nt * 8 + 2 * t;
            *(float2*)&out_attn[ob + (size_t)rowg * Ee + col] =
                make_float2(oacc[nt][0], oacc[nt][1]);
            *(float2*)&out_attn[ob + (size_t)(rowg + 8) * Ee + col] =
                make_float2(oacc[nt][2], oacc[nt][3]);
        }
    }
}

// ---------------------------------------------------------------------------
extern "C" void kernel_launch(void* const* d_in, const int* in_sizes, int n_in,
                              void* d_out, int out_size) {
    const float* query = (const float*)d_in[0];
    const float* key_  = (const float*)d_in[1];
    const float* value = (const float*)d_in[2];
    const float* ab    = (const float*)d_in[3];
    const float* Wq    = (const float*)d_in[4];
    const float* bq    = (const float*)d_in[5];
    const float* Wk    = (const float*)d_in[6];
    const float* bk    = (const float*)d_in[7];
    const float* Wv    = (const float*)d_in[8];
    const float* bv    = (const float*)d_in[9];

    float* out = (float*)d_out;
    const long long attn_elems = (long long)Bc * Nn * Ee;
    const long long w_elems    = (long long)BHn * Nn * Nn;
    float* attn_out = out;
    float* w_out = nullptr;
    if ((long long)out_size >= attn_elems + w_elems) w_out = out + attn_elems;

    {
        dim3 grid(4096, 6);
        pack_kernel<<<grid, 256>>>(query, key_, value, Wq, Wk, Wv);
    }
    {
        cudaFuncSetAttribute(proj_mma_kernel, cudaFuncAttributeMaxDynamicSharedMemorySize,
                             PROJ_SMEM_BYTES);
        dim3 grid(Mtot / 128, Ee / 128, 3);
        proj_mma_kernel<<<grid, 256, PROJ_SMEM_BYTES>>>(bq, bk, bv);
    }
    {
        dim3 grid(8, 64);
        vt_kernel<<<grid, 256>>>();
    }
    {
        cudaFuncSetAttribute(attn_mma_kernel, cudaFuncAttributeMaxDynamicSharedMemorySize,
                             ATTN_SMEM_BYTES);
        dim3 grid(Nn / 32, BHn);
        attn_mma_kernel<<<grid, 512, ATTN_SMEM_BYTES>>>(ab, attn_out, w_out);
    }
}

// round 11
// speedup vs baseline: 1.4859x; 1.4859x over previous
#include <cuda_runtime.h>
#include <cstdint>

#define Bc   4
#define Nn   1024
#define Ee   1024
#define BHn  64
#define Mtot 4096   // B*N

// Projected Q/K as separate hi/lo bf16x2 planes (pair p covers cols 2p,2p+1).
__device__ uint32_t g_qh[Mtot * 512];
__device__ uint32_t g_ql[Mtot * 512];
__device__ uint32_t g_kh[Mtot * 512];
__device__ uint32_t g_kl[Mtot * 512];
__device__ float    g_v [Mtot * Ee];
// V^T packed planes: [bh][d][cpair]  (64 x 64 x 512)
__device__ uint32_t g_vth[64 * 64 * 512];
__device__ uint32_t g_vtl[64 * 64 * 512];
// Packed GEMM input planes: [z][...]
__device__ uint32_t g_pxh[3][Mtot * 512];
__device__ uint32_t g_pxl[3][Mtot * 512];
__device__ uint32_t g_pwh[3][1024 * 512];
__device__ uint32_t g_pwl[3][1024 * 512];
// Fallback weights buffer if the harness output only holds attn.
__device__ float g_w[(size_t)BHn * Nn * Nn];

// ===========================================================================
// helpers
// ===========================================================================
static __device__ __forceinline__ uint32_t smem_u32(const void* p) {
    uint32_t a;
    asm("{ .reg .u64 t; cvta.to.shared.u64 t, %1; cvt.u32.u64 %0, t; }" : "=r"(a) : "l"(p));
    return a;
}
static __device__ __forceinline__ uint32_t pack_bf16(float x0, float x1) {
    uint32_t r;
    asm("cvt.rn.bf16x2.f32 %0, %1, %2;" : "=r"(r) : "f"(x1), "f"(x0));
    return r;
}
static __device__ __forceinline__ void split2(float x0, float x1, uint32_t& h, uint32_t& l) {
    h = pack_bf16(x0, x1);
    float h0 = __uint_as_float(h << 16);
    float h1 = __uint_as_float(h & 0xFFFF0000u);
    l = pack_bf16(x0 - h0, x1 - h1);
}
static __device__ __forceinline__ void mma_bf16(float* c, const uint32_t* a, const uint32_t* b) {
    asm volatile(
        "mma.sync.aligned.m16n8k16.row.col.f32.bf16.bf16.f32 "
        "{%0,%1,%2,%3}, {%4,%5,%6,%7}, {%8,%9}, {%0,%1,%2,%3};"
        : "+f"(c[0]), "+f"(c[1]), "+f"(c[2]), "+f"(c[3])
        : "r"(a[0]), "r"(a[1]), "r"(a[2]), "r"(a[3]), "r"(b[0]), "r"(b[1]));
}
static __device__ __forceinline__ void cp16(uint32_t dst, const void* src) {
    asm volatile("cp.async.cg.shared.global [%0], [%1], 16;" :: "r"(dst), "l"(src));
}
static __device__ __forceinline__ void cp_commit() {
    asm volatile("cp.async.commit_group;" ::: "memory");
}
template<int N> static __device__ __forceinline__ void cp_wait() {
    asm volatile("cp.async.wait_group %0;" :: "n"(N) : "memory");
}

// ===========================================================================
// Pack kernel: fp32 -> separate hi/lo plane pairs for proj inputs.
// ===========================================================================
__global__ __launch_bounds__(256) void pack_kernel(
    const float* __restrict__ xq, const float* __restrict__ xk, const float* __restrict__ xv,
    const float* __restrict__ wq, const float* __restrict__ wk, const float* __restrict__ wv)
{
    const int z = blockIdx.y;
    const float* src; uint32_t* dh; uint32_t* dl; int nf4;
    switch (z) {
        case 0: src = xq; dh = g_pxh[0]; dl = g_pxl[0]; nf4 = Mtot * 256; break;
        case 1: src = xk; dh = g_pxh[1]; dl = g_pxl[1]; nf4 = Mtot * 256; break;
        case 2: src = xv; dh = g_pxh[2]; dl = g_pxl[2]; nf4 = Mtot * 256; break;
        case 3: src = wq; dh = g_pwh[0]; dl = g_pwl[0]; nf4 = 1024 * 256; break;
        case 4: src = wk; dh = g_pwh[1]; dl = g_pwl[1]; nf4 = 1024 * 256; break;
        default: src = wv; dh = g_pwh[2]; dl = g_pwl[2]; nf4 = 1024 * 256; break;
    }
    int i = blockIdx.x * 256 + threadIdx.x;
    if (i >= nf4) return;
    float4 v = *(const float4*)(src + (size_t)i * 4);
    uint32_t h0, l0, h1, l1;
    split2(v.x, v.y, h0, l0);
    split2(v.z, v.w, h1, l1);
    *(uint2*)&dh[2 * i] = make_uint2(h0, h1);
    *(uint2*)&dl[2 * i] = make_uint2(l0, l1);
}

// ===========================================================================
// Projection GEMM: C = X @ W^T + b, cp.async double-buffered, 2 CTAs/SM.
// PSP=20 (16 used + 4 pad): banks 20g+t mod 32 all distinct -> conflict-free.
// ===========================================================================
#define PSP 20
#define PSTAGE (4 * 128 * PSP)                      // 10240 words
#define PROJ_SMEM_BYTES ((2 * PSTAGE + 128) * 4)    // 82432

__global__ __launch_bounds__(256, 2) void proj_mma_kernel(
    const float* __restrict__ bq, const float* __restrict__ bk, const float* __restrict__ bv)
{
    extern __shared__ uint32_t psm[];
    float* bsm = (float*)(psm + 2 * PSTAGE);
    const uint32_t smb = smem_u32(psm);

    const int z = blockIdx.z;
    const uint32_t* xh = g_pxh[z]; const uint32_t* xl = g_pxl[z];
    const uint32_t* wh = g_pwh[z]; const uint32_t* wl = g_pwl[z];
    const float* bias = (z == 0) ? bq : (z == 1) ? bk : bv;

    const int tid = threadIdx.x;
    const int w = tid >> 5, lane = tid & 31;
    const int g = lane >> 2, t = lane & 3;
    const int bm = blockIdx.x * 128, bn = blockIdx.y * 128;
    const int wm = w >> 2, wn = w & 3;

    if (tid < 128) bsm[tid] = bias[bn + tid];

    auto issueP = [&](int kc) {
        int st = kc & 1;
        #pragma unroll
        for (int s = 0; s < 8; s++) {
            int idx = tid + 256 * s;          // 0..2047
            int plane = idx >> 9;
            int row = (idx >> 2) & 127;
            int seg = idx & 3;
            const uint32_t* src;
            if (plane == 0)      src = xh + (size_t)(bm + row) * 512 + kc * 16 + seg * 4;
            else if (plane == 1) src = xl + (size_t)(bm + row) * 512 + kc * 16 + seg * 4;
            else if (plane == 2) src = wh + (size_t)(bn + row) * 512 + kc * 16 + seg * 4;
            else                 src = wl + (size_t)(bn + row) * 512 + kc * 16 + seg * 4;
            cp16(smb + (uint32_t)(st * PSTAGE + plane * 128 * PSP + row * PSP + seg * 4) * 4, src);
        }
        cp_commit();
    };

    issueP(0);
    issueP(1);

    float acc[4][4][4];
    #pragma unroll
    for (int i = 0; i < 4; i++)
        #pragma unroll
        for (int j = 0; j < 4; j++)
            #pragma unroll
            for (int k = 0; k < 4; k++) acc[i][j][k] = 0.0f;

    #pragma unroll 1
    for (int kc = 0; kc < 32; kc++) {
        if (kc == 31) cp_wait<0>(); else cp_wait<1>();
        __syncthreads();
        const uint32_t* XH = psm + (kc & 1) * PSTAGE;
        const uint32_t* XL = XH + 128 * PSP;
        const uint32_t* WH = XH + 2 * 128 * PSP;
        const uint32_t* WL = XH + 3 * 128 * PSP;

        #pragma unroll
        for (int ks = 0; ks < 2; ks++) {
            uint32_t bhf[4][2], blf[4][2];
            #pragma unroll
            for (int nt = 0; nt < 4; nt++) {
                int rb = (wn * 32 + nt * 8 + g) * PSP + ks * 8 + t;
                bhf[nt][0] = WH[rb]; bhf[nt][1] = WH[rb + 4];
                blf[nt][0] = WL[rb]; blf[nt][1] = WL[rb + 4];
            }
            #pragma unroll
            for (int mt = 0; mt < 4; mt++) {
                int ra = (wm * 64 + mt * 16 + g) * PSP + ks * 8 + t;
                uint32_t ah[4] = {XH[ra], XH[ra + 8 * PSP], XH[ra + 4], XH[ra + 8 * PSP + 4]};
                uint32_t al[4] = {XL[ra], XL[ra + 8 * PSP], XL[ra + 4], XL[ra + 8 * PSP + 4]};
                #pragma unroll
                for (int nt = 0; nt < 4; nt++) {
                    mma_bf16(acc[mt][nt], ah, bhf[nt]);
                    mma_bf16(acc[mt][nt], ah, blf[nt]);
                    mma_bf16(acc[mt][nt], al, bhf[nt]);
                }
            }
        }
        __syncthreads();
        if (kc < 30) issueP(kc + 2);
    }

    #pragma unroll
    for (int mt = 0; mt < 4; mt++) {
        int row = wm * 64 + mt * 16 + g;
        #pragma unroll
        for (int nt = 0; nt < 4; nt++) {
            int col = wn * 32 + nt * 8 + 2 * t;
            float bx = bsm[col], by = bsm[col + 1];
            float c00 = acc[mt][nt][0] + bx, c01 = acc[mt][nt][1] + by;
            float c10 = acc[mt][nt][2] + bx, c11 = acc[mt][nt][3] + by;
            if (z < 2) {
                uint32_t* dh = (z == 0) ? g_qh : g_kh;
                uint32_t* dl = (z == 0) ? g_ql : g_kl;
                size_t p0 = (size_t)(bm + row) * 512 + ((bn + col) >> 1);
                size_t p1 = (size_t)(bm + row + 8) * 512 + ((bn + col) >> 1);
                uint32_t h, l;
                split2(c00, c01, h, l);
                dh[p0] = h; dl[p0] = l;
                split2(c10, c11, h, l);
                dh[p1] = h; dl[p1] = l;
            } else {
                *(float2*)(g_v + (size_t)(bm + row) * 1024 + bn + col) = make_float2(c00, c01);
                *(float2*)(g_v + (size_t)(bm + row + 8) * 1024 + bn + col) = make_float2(c10, c11);
            }
        }
    }
}

// ===========================================================================
// V transpose+pack: g_v (natural) -> g_vth/g_vtl [bh][d][cpair].
// ===========================================================================
__global__ __launch_bounds__(256) void vt_kernel()
{
    __shared__ uint32_t sh[64 * 65], sl[64 * 65];
    const int bh = blockIdx.y, ct = blockIdx.x, tid = threadIdx.x;

    #pragma unroll
    for (int s = 0; s < 16; s++) {
        int idx = tid + 256 * s;
        int d = idx & 63, cp = idx >> 6;
        const float* p = g_v + (size_t)(ct * 128 + 2 * cp) * 4096 + bh * 64 + d;
        float x0 = p[0], x1 = p[4096];
        uint32_t h, l;
        split2(x0, x1, h, l);
        sh[cp * 65 + d] = h;
        sl[cp * 65 + d] = l;
    }
    __syncthreads();
    #pragma unroll
    for (int s = 0; s < 16; s++) {
        int idx = tid + 256 * s;
        int cp = idx & 63, d = idx >> 6;
        size_t o = ((size_t)(bh * 64 + d) << 9) + ct * 64 + cp;
        g_vth[o] = sh[cp * 65 + d];
        g_vtl[o] = sl[cp * 65 + d];
    }
}

// ===========================================================================
// Attention: register-resident scores; P packed per-tile inside AV loop.
// (round-9 layout: K rows stride 36, V rows stride 68, scalar frag loads)
// ===========================================================================
#define KV_W   0
#define QH_W   18432
#define QL_W   (QH_W + 1152)
#define SCRM_W (QL_W + 1152)
#define SCRS_W (SCRM_W + 256)
#define ATTN_SMEM_WORDS 21256
#define ATTN_SMEM_BYTES (ATTN_SMEM_WORDS * 4)   // 85024

__global__ __launch_bounds__(512, 1) void attn_mma_kernel(
    const float* __restrict__ bias, float* __restrict__ out_attn, float* __restrict__ w_out)
{
    extern __shared__ float sm[];
    uint32_t* KV = (uint32_t*)sm + KV_W;
    uint32_t* QH = (uint32_t*)sm + QH_W;
    uint32_t* QL = (uint32_t*)sm + QL_W;
    float* scrM = sm + SCRM_W;
    float* scrS = sm + SCRS_W;
    const uint32_t smb = smem_u32(sm);

    const int tid = threadIdx.x;
    const int w = tid >> 5, lane = tid & 31;
    const int g = lane >> 2, t = lane & 3;
    const int wm = w >> 3, wn = w & 7;
    const int m0 = wm * 16, n0 = wn * 16;
    const int bh = blockIdx.y;
    const int r0 = blockIdx.x * 32;

    const float* bsrc = bias + (size_t)(bh & 3) * Nn * Nn;
    float* wbase = (w_out != nullptr) ? w_out : g_w;
    float* wrow_base = wbase + (size_t)bh * Nn * Nn;

    auto issueK = [&](int it) {
        int b = it & 1;
        #pragma unroll
        for (int s = 0; s < 4; s++) {
            int idx = tid + 512 * s;
            int plane = idx >> 10;
            int row = (idx >> 3) & 127;
            int seg = idx & 7;
            const uint32_t* src = (plane ? g_kl : g_kh) +
                (size_t)(it * 128 + row) * 2048 + bh * 32 + seg * 4;
            cp16(smb + (uint32_t)(KV_W + b * 9216 + plane * 4608 + row * 36 + seg * 4) * 4, src);
        }
        cp_commit();
    };
    auto issueV = [&](int it) {
        int b = it & 1;
        #pragma unroll
        for (int s = 0; s < 4; s++) {
            int idx = tid + 512 * s;
            int plane = idx >> 10;
            int row = (idx >> 4) & 63;
            int seg = idx & 15;
            const uint32_t* src = (plane ? g_vtl : g_vth) +
                (((size_t)(bh * 64 + row)) << 9) + it * 64 + seg * 4;
            cp16(smb + (uint32_t)(KV_W + b * 8704 + plane * 4352 + row * 68 + seg * 4) * 4, src);
        }
        cp_commit();
    };

    // ---- prologue: Q, K0, K1 ----
    {
        int plane = tid >> 8, ci = tid & 255, row = ci >> 3, seg = ci & 7;
        const uint32_t* src = (plane ? g_ql : g_qh) +
            (size_t)(r0 + row) * 2048 + bh * 32 + seg * 4;
        cp16(smb + (uint32_t)((plane ? QL_W : QH_W) + row * 36 + seg * 4) * 4, src);
        cp_commit();
    }
    issueK(0);
    issueK(1);

    cp_wait<2>();
    __syncthreads();
    uint32_t qah[4][4], qal[4][4];
    #pragma unroll
    for (int ks = 0; ks < 4; ks++) {
        int ra = (m0 + g) * 36 + ks * 8 + t;
        qah[ks][0] = QH[ra];     qah[ks][1] = QH[ra + 288];
        qah[ks][2] = QH[ra + 4]; qah[ks][3] = QH[ra + 292];
        qal[ks][0] = QL[ra];     qal[ks][1] = QL[ra + 288];
        qal[ks][2] = QL[ra + 4]; qal[ks][3] = QL[ra + 292];
    }

    // ---- scores into registers (64 floats/thread) ----
    float sv[64];
    #pragma unroll
    for (int j = 0; j < 64; j++) sv[j] = 0.0f;

    const int rowg = r0 + m0 + g;

    #pragma unroll
    for (int it = 0; it < 8; it++) {
        if (it == 7) cp_wait<0>(); else cp_wait<1>();
        __syncthreads();
        const uint32_t* KHb = KV + (it & 1) * 9216;
        const uint32_t* KLb = KHb + 4608;
        float* s = sv + it * 8;

        #pragma unroll
        for (int ks = 0; ks < 4; ks++) {
            int rb0 = (n0 + g) * 36 + ks * 8 + t;
            int rb1 = (n0 + 8 + g) * 36 + ks * 8 + t;
            uint32_t bh0[2] = {KHb[rb0], KHb[rb0 + 4]};
            uint32_t bl0[2] = {KLb[rb0], KLb[rb0 + 4]};
            uint32_t bh1[2] = {KHb[rb1], KHb[rb1 + 4]};
            uint32_t bl1[2] = {KLb[rb1], KLb[rb1 + 4]};
            mma_bf16(s,     qah[ks], bh0);
            mma_bf16(s,     qah[ks], bl0);
            mma_bf16(s,     qal[ks], bh0);
            mma_bf16(s + 4, qah[ks], bh1);
            mma_bf16(s + 4, qah[ks], bl1);
            mma_bf16(s + 4, qal[ks], bh1);
        }
        {
            int c0 = it * 128 + n0 + 2 * t;
            int c1 = c0 + 8;
            float2 b00 = *(const float2*)(bsrc + (size_t)rowg * 1024 + c0);
            float2 b01 = *(const float2*)(bsrc + (size_t)(rowg + 8) * 1024 + c0);
            float2 b10 = *(const float2*)(bsrc + (size_t)rowg * 1024 + c1);
            float2 b11 = *(const float2*)(bsrc + (size_t)(rowg + 8) * 1024 + c1);
            s[0] += b00.x; s[1] += b00.y;
            s[2] += b01.x; s[3] += b01.y;
            s[4] += b10.x; s[5] += b10.y;
            s[6] += b11.x; s[7] += b11.y;
        }
        __syncthreads();
        if (it < 6) issueK(it + 2);
    }

    // ---- V pipeline prologue (overlaps softmax) ----
    issueV(0);
    issueV(1);

    // ---- softmax: quad shuffle + cross-warp smem reduce ----
    float mg = -3.0e38f, mg8 = -3.0e38f;
    #pragma unroll
    for (int it = 0; it < 8; it++) {
        float* s = sv + it * 8;
        mg  = fmaxf(mg,  fmaxf(fmaxf(s[0], s[1]), fmaxf(s[4], s[5])));
        mg8 = fmaxf(mg8, fmaxf(fmaxf(s[2], s[3]), fmaxf(s[6], s[7])));
    }
    mg  = fmaxf(mg,  __shfl_xor_sync(0xffffffffu, mg, 1));
    mg  = fmaxf(mg,  __shfl_xor_sync(0xffffffffu, mg, 2));
    mg8 = fmaxf(mg8, __shfl_xor_sync(0xffffffffu, mg8, 1));
    mg8 = fmaxf(mg8, __shfl_xor_sync(0xffffffffu, mg8, 2));
    if (t == 0) {
        scrM[(m0 + g) * 8 + wn]     = mg;
        scrM[(m0 + g + 8) * 8 + wn] = mg8;
    }
    __syncthreads();
    float Mg = -3.0e38f, Mg8 = -3.0e38f;
    #pragma unroll
    for (int k = 0; k < 8; k++) {
        Mg  = fmaxf(Mg,  scrM[(m0 + g) * 8 + k]);
        Mg8 = fmaxf(Mg8, scrM[(m0 + g + 8) * 8 + k]);
    }
    float sg = 0.0f, sg8 = 0.0f;
    #pragma unroll
    for (int it = 0; it < 8; it++) {
        float* s = sv + it * 8;
        s[0] = __expf(s[0] - Mg);  s[1] = __expf(s[1] - Mg);
        s[4] = __expf(s[4] - Mg);  s[5] = __expf(s[5] - Mg);
        s[2] = __expf(s[2] - Mg8); s[3] = __expf(s[3] - Mg8);
        s[6] = __expf(s[6] - Mg8); s[7] = __expf(s[7] - Mg8);
        sg  += s[0] + s[1] + s[4] + s[5];
        sg8 += s[2] + s[3] + s[6] + s[7];
    }
    sg  += __shfl_xor_sync(0xffffffffu, sg, 1);
    sg  += __shfl_xor_sync(0xffffffffu, sg, 2);
    sg8 += __shfl_xor_sync(0xffffffffu, sg8, 1);
    sg8 += __shfl_xor_sync(0xffffffffu, sg8, 2);
    if (t == 0) {
        scrS[(m0 + g) * 8 + wn]     = sg;
        scrS[(m0 + g + 8) * 8 + wn] = sg8;
    }
    __syncthreads();
    float Sg = 0.0f, Sg8 = 0.0f;
    #pragma unroll
    for (int k = 0; k < 8; k++) {
        Sg  += scrS[(m0 + g) * 8 + k];
        Sg8 += scrS[(m0 + g + 8) * 8 + k];
    }
    const float invg = 1.0f / Sg, invg8 = 1.0f / Sg8;

    // ---- AV loop: per-tile P scale + weights-store + pack + MMA ----
    float* wr0 = wrow_base + (size_t)rowg * 1024;
    float* wr8 = wrow_base + (size_t)(rowg + 8) * 1024;

    float oacc[8][4];
    #pragma unroll
    for (int i = 0; i < 8; i++)
        #pragma unroll
        for (int j = 0; j < 4; j++) oacc[i][j] = 0.0f;

    #pragma unroll
    for (int it = 0; it < 8; it++) {
        if (it == 7) cp_wait<0>(); else cp_wait<1>();
        __syncthreads();
        const uint32_t* VHb = KV + (it & 1) * 8704;
        const uint32_t* VLb = VHb + 4352;

        float* s = sv + it * 8;
        float p0 = s[0] * invg,  p1 = s[1] * invg;
        float p2 = s[2] * invg8, p3 = s[3] * invg8;
        float p4 = s[4] * invg,  p5 = s[5] * invg;
        float p6 = s[6] * invg8, p7 = s[7] * invg8;
        int c0 = it * 128 + n0 + 2 * t;
        *(float2*)&wr0[c0]     = make_float2(p0, p1);
        *(float2*)&wr8[c0]     = make_float2(p2, p3);
        *(float2*)&wr0[c0 + 8] = make_float2(p4, p5);
        *(float2*)&wr8[c0 + 8] = make_float2(p6, p7);
        uint32_t pah[4], pal[4];
        split2(p0, p1, pah[0], pal[0]);
        split2(p2, p3, pah[1], pal[1]);
        split2(p4, p5, pah[2], pal[2]);
        split2(p6, p7, pah[3], pal[3]);

        #pragma unroll
        for (int nt = 0; nt < 8; nt++) {
            int rb = (nt * 8 + g) * 68 + wn * 8 + t;
            uint32_t bh2[2] = {VHb[rb], VHb[rb + 4]};
            uint32_t bl2[2] = {VLb[rb], VLb[rb + 4]};
            mma_bf16(oacc[nt], pah, bh2);
            mma_bf16(oacc[nt], pah, bl2);
            mma_bf16(oacc[nt], pal, bh2);
        }
        __syncthreads();
        if (it < 6) issueV(it + 2);
    }

    // ---- tree-reduce 8 wn-partials (overlay on KV region) ----
    __syncthreads();
    float* red = sm + KV_W;
    auto stPart = [&](int b) {
        int base = b * 2176 + wm * 1088;
        #pragma unroll
        for (int nt = 0; nt < 8; nt++) {
            *(float2*)&red[base + g * 66 + nt * 8 + 2 * t] =
                make_float2(oacc[nt][0], oacc[nt][1]);
            *(float2*)&red[base + (g + 8) * 66 + nt * 8 + 2 * t] =
                make_float2(oacc[nt][2], oacc[nt][3]);
        }
    };
    auto addPart = [&](int b) {
        int base = b * 2176 + wm * 1088;
        #pragma unroll
        for (int nt = 0; nt < 8; nt++) {
            float2 p0 = *(float2*)&red[base + g * 66 + nt * 8 + 2 * t];
            float2 p1 = *(float2*)&red[base + (g + 8) * 66 + nt * 8 + 2 * t];
            oacc[nt][0] += p0.x; oacc[nt][1] += p0.y;
            oacc[nt][2] += p1.x; oacc[nt][3] += p1.y;
        }
    };
    if (wn >= 4) stPart(wn - 4);
    __syncthreads();
    if (wn < 4) addPart(wn);
    __syncthreads();
    if (wn == 2 || wn == 3) stPart(wn - 2);
    __syncthreads();
    if (wn < 2) addPart(wn);
    __syncthreads();
    if (wn == 1) stPart(0);
    __syncthreads();
    if (wn == 0) {
        addPart(0);
        size_t ob = (size_t)(bh >> 4) * Nn * Ee + (size_t)(bh & 15) * 64;
        #pragma unroll
        for (int nt = 0; nt < 8; nt++) {
            int col = nt * 8 + 2 * t;
            *(float2*)&out_attn[ob + (size_t)rowg * Ee + col] =
                make_float2(oacc[nt][0], oacc[nt][1]);
            *(float2*)&out_attn[ob + (size_t)(rowg + 8) * Ee + col] =
                make_float2(oacc[nt][2], oacc[nt][3]);
        }
    }
}

// ---------------------------------------------------------------------------
extern "C" void kernel_launch(void* const* d_in, const int* in_sizes, int n_in,
                              void* d_out, int out_size) {
    const float* query = (const float*)d_in[0];
    const float* key_  = (const float*)d_in[1];
    const float* value = (const float*)d_in[2];
    const float* ab    = (const float*)d_in[3];
    const float* Wq    = (const float*)d_in[4];
    const float* bq    = (const float*)d_in[5];
    const float* Wk    = (const float*)d_in[6];
    const float* bk    = (const float*)d_in[7];
    const float* Wv    = (const float*)d_in[8];
    const float* bv    = (const float*)d_in[9];

    float* out = (float*)d_out;
    const long long attn_elems = (long long)Bc * Nn * Ee;
    const long long w_elems    = (long long)BHn * Nn * Nn;
    float* attn_out = out;
    float* w_out = nullptr;
    if ((long long)out_size >= attn_elems + w_elems) w_out = out + attn_elems;

    {
        dim3 grid(4096, 6);
        pack_kernel<<<grid, 256>>>(query, key_, value, Wq, Wk, Wv);
    }
    {
        cudaFuncSetAttribute(proj_mma_kernel, cudaFuncAttributeMaxDynamicSharedMemorySize,
                             PROJ_SMEM_BYTES);
        dim3 grid(Mtot / 128, Ee / 128, 3);
        proj_mma_kernel<<<grid, 256, PROJ_SMEM_BYTES>>>(bq, bk, bv);
    }
    {
        dim3 grid(8, 64);
        vt_kernel<<<grid, 256>>>();
    }
    {
        cudaFuncSetAttribute(attn_mma_kernel, cudaFuncAttributeMaxDynamicSharedMemorySize,
                             ATTN_SMEM_BYTES);
        dim3 grid(Nn / 32, BHn);
        attn_mma_kernel<<<grid, 512, ATTN_SMEM_BYTES>>>(ab, attn_out, w_out);
    }
}

// round 12
// speedup vs baseline: 1.5504x; 1.0434x over previous
#include <cuda_runtime.h>
#include <cstdint>

#define Bc   4
#define Nn   1024
#define Ee   1024
#define BHn  64
#define Mtot 4096   // B*N

// Projected Q/K as separate hi/lo bf16x2 planes (pair p covers cols 2p,2p+1).
__device__ uint32_t g_qh[Mtot * 512];
__device__ uint32_t g_ql[Mtot * 512];
__device__ uint32_t g_kh[Mtot * 512];
__device__ uint32_t g_kl[Mtot * 512];
__device__ float    g_v [Mtot * Ee];
// V^T packed planes: [bh][d][cpair]  (64 x 64 x 512)
__device__ uint32_t g_vth[64 * 64 * 512];
__device__ uint32_t g_vtl[64 * 64 * 512];
// Packed GEMM input planes: [z][...]
__device__ uint32_t g_pxh[3][Mtot * 512];
__device__ uint32_t g_pxl[3][Mtot * 512];
__device__ uint32_t g_pwh[3][1024 * 512];
__device__ uint32_t g_pwl[3][1024 * 512];
// Fallback weights buffer if the harness output only holds attn.
__device__ float g_w[(size_t)BHn * Nn * Nn];

// ===========================================================================
// helpers
// ===========================================================================
static __device__ __forceinline__ uint32_t smem_u32(const void* p) {
    uint32_t a;
    asm("{ .reg .u64 t; cvta.to.shared.u64 t, %1; cvt.u32.u64 %0, t; }" : "=r"(a) : "l"(p));
    return a;
}
static __device__ __forceinline__ uint32_t pack_bf16(float x0, float x1) {
    uint32_t r;
    asm("cvt.rn.bf16x2.f32 %0, %1, %2;" : "=r"(r) : "f"(x1), "f"(x0));
    return r;
}
static __device__ __forceinline__ void split2(float x0, float x1, uint32_t& h, uint32_t& l) {
    h = pack_bf16(x0, x1);
    float h0 = __uint_as_float(h << 16);
    float h1 = __uint_as_float(h & 0xFFFF0000u);
    l = pack_bf16(x0 - h0, x1 - h1);
}
static __device__ __forceinline__ void mma_bf16(float* c, const uint32_t* a, const uint32_t* b) {
    asm volatile(
        "mma.sync.aligned.m16n8k16.row.col.f32.bf16.bf16.f32 "
        "{%0,%1,%2,%3}, {%4,%5,%6,%7}, {%8,%9}, {%0,%1,%2,%3};"
        : "+f"(c[0]), "+f"(c[1]), "+f"(c[2]), "+f"(c[3])
        : "r"(a[0]), "r"(a[1]), "r"(a[2]), "r"(a[3]), "r"(b[0]), "r"(b[1]));
}
static __device__ __forceinline__ void ldsm_x4(uint32_t* r, uint32_t addr) {
    asm volatile("ldmatrix.sync.aligned.m8n8.x4.shared.b16 {%0,%1,%2,%3}, [%4];"
                 : "=r"(r[0]), "=r"(r[1]), "=r"(r[2]), "=r"(r[3]) : "r"(addr));
}
static __device__ __forceinline__ void cp16(uint32_t dst, const void* src) {
    asm volatile("cp.async.cg.shared.global [%0], [%1], 16;" :: "r"(dst), "l"(src));
}
static __device__ __forceinline__ void cp_commit() {
    asm volatile("cp.async.commit_group;" ::: "memory");
}
template<int N> static __device__ __forceinline__ void cp_wait() {
    asm volatile("cp.async.wait_group %0;" :: "n"(N) : "memory");
}

// ===========================================================================
// Pack kernel: fp32 -> separate hi/lo plane pairs for proj inputs.
// ===========================================================================
__global__ __launch_bounds__(256) void pack_kernel(
    const float* __restrict__ xq, const float* __restrict__ xk, const float* __restrict__ xv,
    const float* __restrict__ wq, const float* __restrict__ wk, const float* __restrict__ wv)
{
    const int z = blockIdx.y;
    const float* src; uint32_t* dh; uint32_t* dl; int nf4;
    switch (z) {
        case 0: src = xq; dh = g_pxh[0]; dl = g_pxl[0]; nf4 = Mtot * 256; break;
        case 1: src = xk; dh = g_pxh[1]; dl = g_pxl[1]; nf4 = Mtot * 256; break;
        case 2: src = xv; dh = g_pxh[2]; dl = g_pxl[2]; nf4 = Mtot * 256; break;
        case 3: src = wq; dh = g_pwh[0]; dl = g_pwl[0]; nf4 = 1024 * 256; break;
        case 4: src = wk; dh = g_pwh[1]; dl = g_pwl[1]; nf4 = 1024 * 256; break;
        default: src = wv; dh = g_pwh[2]; dl = g_pwl[2]; nf4 = 1024 * 256; break;
    }
    int i = blockIdx.x * 256 + threadIdx.x;
    if (i >= nf4) return;
    float4 v = *(const float4*)(src + (size_t)i * 4);
    uint32_t h0, l0, h1, l1;
    split2(v.x, v.y, h0, l0);
    split2(v.z, v.w, h1, l1);
    *(uint2*)&dh[2 * i] = make_uint2(h0, h1);
    *(uint2*)&dl[2 * i] = make_uint2(l0, l1);
}

// ===========================================================================
// Projection GEMM: C = X @ W^T + b, cp.async double-buffered, 2 CTAs/SM.
// Fragment loads via ldmatrix.x4 (stride 20: banks 20r mod 32 distinct).
// ===========================================================================
#define PSP 20
#define PSTAGE (4 * 128 * PSP)                      // 10240 words
#define PROJ_SMEM_BYTES ((2 * PSTAGE + 128) * 4)    // 82432

__global__ __launch_bounds__(256, 2) void proj_mma_kernel(
    const float* __restrict__ bq, const float* __restrict__ bk, const float* __restrict__ bv)
{
    extern __shared__ uint32_t psm[];
    float* bsm = (float*)(psm + 2 * PSTAGE);
    const uint32_t smb = smem_u32(psm);

    const int z = blockIdx.z;
    const uint32_t* xh = g_pxh[z]; const uint32_t* xl = g_pxl[z];
    const uint32_t* wh = g_pwh[z]; const uint32_t* wl = g_pwl[z];
    const float* bias = (z == 0) ? bq : (z == 1) ? bk : bv;

    const int tid = threadIdx.x;
    const int w = tid >> 5, lane = tid & 31;
    const int g = lane >> 2, t = lane & 3;
    const int l8 = lane & 7;
    const int bm = blockIdx.x * 128, bn = blockIdx.y * 128;
    const int wm = w >> 2, wn = w & 3;

    if (tid < 128) bsm[tid] = bias[bn + tid];

    // ldmatrix lane bases (word offsets within a plane)
    const int pafb = (wm * 64 + ((lane >> 3) & 1) * 8 + l8) * PSP + ((lane >> 4) & 1) * 4;
    const int pbfb = (wn * 32 + ((lane >> 4) & 1) * 8 + l8) * PSP + ((lane >> 3) & 1) * 4;

    auto issueP = [&](int kc) {
        int st = kc & 1;
        #pragma unroll
        for (int s = 0; s < 8; s++) {
            int idx = tid + 256 * s;          // 0..2047
            int plane = idx >> 9;
            int row = (idx >> 2) & 127;
            int seg = idx & 3;
            const uint32_t* src;
            if (plane == 0)      src = xh + (size_t)(bm + row) * 512 + kc * 16 + seg * 4;
            else if (plane == 1) src = xl + (size_t)(bm + row) * 512 + kc * 16 + seg * 4;
            else if (plane == 2) src = wh + (size_t)(bn + row) * 512 + kc * 16 + seg * 4;
            else                 src = wl + (size_t)(bn + row) * 512 + kc * 16 + seg * 4;
            cp16(smb + (uint32_t)(st * PSTAGE + plane * 128 * PSP + row * PSP + seg * 4) * 4, src);
        }
        cp_commit();
    };

    issueP(0);
    issueP(1);

    float acc[4][4][4];
    #pragma unroll
    for (int i = 0; i < 4; i++)
        #pragma unroll
        for (int j = 0; j < 4; j++)
            #pragma unroll
            for (int k = 0; k < 4; k++) acc[i][j][k] = 0.0f;

    #pragma unroll 1
    for (int kc = 0; kc < 32; kc++) {
        if (kc == 31) cp_wait<0>(); else cp_wait<1>();
        __syncthreads();
        const uint32_t stA = smb + (uint32_t)((kc & 1) * PSTAGE) * 4;
        const uint32_t XHa = stA;
        const uint32_t XLa = stA + (uint32_t)(128 * PSP) * 4;
        const uint32_t WHa = stA + (uint32_t)(2 * 128 * PSP) * 4;
        const uint32_t WLa = stA + (uint32_t)(3 * 128 * PSP) * 4;

        #pragma unroll
        for (int ks = 0; ks < 2; ks++) {
            uint32_t wbh[8], wbl[8];
            ldsm_x4(wbh,     WHa + (uint32_t)(pbfb + ks * 8) * 4);
            ldsm_x4(wbh + 4, WHa + (uint32_t)(pbfb + 16 * PSP + ks * 8) * 4);
            ldsm_x4(wbl,     WLa + (uint32_t)(pbfb + ks * 8) * 4);
            ldsm_x4(wbl + 4, WLa + (uint32_t)(pbfb + 16 * PSP + ks * 8) * 4);
            #pragma unroll
            for (int mt = 0; mt < 4; mt++) {
                uint32_t ah[4], al[4];
                ldsm_x4(ah, XHa + (uint32_t)(pafb + mt * 16 * PSP + ks * 8) * 4);
                ldsm_x4(al, XLa + (uint32_t)(pafb + mt * 16 * PSP + ks * 8) * 4);
                #pragma unroll
                for (int nt = 0; nt < 4; nt++) {
                    mma_bf16(acc[mt][nt], ah, &wbh[nt * 2]);
                    mma_bf16(acc[mt][nt], ah, &wbl[nt * 2]);
                    mma_bf16(acc[mt][nt], al, &wbh[nt * 2]);
                }
            }
        }
        __syncthreads();
        if (kc < 30) issueP(kc + 2);
    }

    #pragma unroll
    for (int mt = 0; mt < 4; mt++) {
        int row = wm * 64 + mt * 16 + g;
        #pragma unroll
        for (int nt = 0; nt < 4; nt++) {
            int col = wn * 32 + nt * 8 + 2 * t;
            float bx = bsm[col], by = bsm[col + 1];
            float c00 = acc[mt][nt][0] + bx, c01 = acc[mt][nt][1] + by;
            float c10 = acc[mt][nt][2] + bx, c11 = acc[mt][nt][3] + by;
            if (z < 2) {
                uint32_t* dh = (z == 0) ? g_qh : g_kh;
                uint32_t* dl = (z == 0) ? g_ql : g_kl;
                size_t p0 = (size_t)(bm + row) * 512 + ((bn + col) >> 1);
                size_t p1 = (size_t)(bm + row + 8) * 512 + ((bn + col) >> 1);
                uint32_t h, l;
                split2(c00, c01, h, l);
                dh[p0] = h; dl[p0] = l;
                split2(c10, c11, h, l);
                dh[p1] = h; dl[p1] = l;
            } else {
                *(float2*)(g_v + (size_t)(bm + row) * 1024 + bn + col) = make_float2(c00, c01);
                *(float2*)(g_v + (size_t)(bm + row + 8) * 1024 + bn + col) = make_float2(c10, c11);
            }
        }
    }
}

// ===========================================================================
// V transpose+pack: g_v (natural) -> g_vth/g_vtl [bh][d][cpair].
// ===========================================================================
__global__ __launch_bounds__(256) void vt_kernel()
{
    __shared__ uint32_t sh[64 * 65], sl[64 * 65];
    const int bh = blockIdx.y, ct = blockIdx.x, tid = threadIdx.x;

    #pragma unroll
    for (int s = 0; s < 16; s++) {
        int idx = tid + 256 * s;
        int d = idx & 63, cp = idx >> 6;
        const float* p = g_v + (size_t)(ct * 128 + 2 * cp) * 4096 + bh * 64 + d;
        float x0 = p[0], x1 = p[4096];
        uint32_t h, l;
        split2(x0, x1, h, l);
        sh[cp * 65 + d] = h;
        sl[cp * 65 + d] = l;
    }
    __syncthreads();
    #pragma unroll
    for (int s = 0; s < 16; s++) {
        int idx = tid + 256 * s;
        int cp = idx & 63, d = idx >> 6;
        size_t o = ((size_t)(bh * 64 + d) << 9) + ct * 64 + cp;
        g_vth[o] = sh[cp * 65 + d];
        g_vtl[o] = sl[cp * 65 + d];
    }
}

// ===========================================================================
// Attention: register-resident scores; ldmatrix fragment loads.
// ===========================================================================
#define KV_W   0
#define QH_W   18432
#define QL_W   (QH_W + 1152)
#define SCRM_W (QL_W + 1152)
#define SCRS_W (SCRM_W + 256)
#define ATTN_SMEM_WORDS 21256
#define ATTN_SMEM_BYTES (ATTN_SMEM_WORDS * 4)   // 85024

__global__ __launch_bounds__(512, 1) void attn_mma_kernel(
    const float* __restrict__ bias, float* __restrict__ out_attn, float* __restrict__ w_out)
{
    extern __shared__ float sm[];
    float* scrM = sm + SCRM_W;
    float* scrS = sm + SCRS_W;
    const uint32_t smb = smem_u32(sm);

    const int tid = threadIdx.x;
    const int w = tid >> 5, lane = tid & 31;
    const int g = lane >> 2, t = lane & 3;
    const int l8 = lane & 7;
    const int wm = w >> 3, wn = w & 7;
    const int m0 = wm * 16, n0 = wn * 16;
    const int bh = blockIdx.y;
    const int r0 = blockIdx.x * 32;

    const float* bsrc = bias + (size_t)(bh & 3) * Nn * Nn;
    float* wbase = (w_out != nullptr) ? w_out : g_w;
    float* wrow_base = wbase + (size_t)bh * Nn * Nn;

    // ldmatrix lane bases (word offsets)
    const int qfb = (m0 + ((lane >> 3) & 1) * 8 + l8) * 36 + ((lane >> 4) & 1) * 4;
    const int kfb = (n0 + ((lane >> 4) & 1) * 8 + l8) * 36 + ((lane >> 3) & 1) * 4;
    const int vfb = (((lane >> 4) & 1) * 8 + l8) * 68 + wn * 8 + ((lane >> 3) & 1) * 4;

    auto issueK = [&](int it) {
        int b = it & 1;
        #pragma unroll
        for (int s = 0; s < 4; s++) {
            int idx = tid + 512 * s;
            int plane = idx >> 10;
            int row = (idx >> 3) & 127;
            int seg = idx & 7;
            const uint32_t* src = (plane ? g_kl : g_kh) +
                (size_t)(it * 128 + row) * 2048 + bh * 32 + seg * 4;
            cp16(smb + (uint32_t)(KV_W + b * 9216 + plane * 4608 + row * 36 + seg * 4) * 4, src);
        }
        cp_commit();
    };
    auto issueV = [&](int it) {
        int b = it & 1;
        #pragma unroll
        for (int s = 0; s < 4; s++) {
            int idx = tid + 512 * s;
            int plane = idx >> 10;
            int row = (idx >> 4) & 63;
            int seg = idx & 15;
            const uint32_t* src = (plane ? g_vtl : g_vth) +
                (((size_t)(bh * 64 + row)) << 9) + it * 64 + seg * 4;
            cp16(smb + (uint32_t)(KV_W + b * 8704 + plane * 4352 + row * 68 + seg * 4) * 4, src);
        }
        cp_commit();
    };

    // ---- prologue: Q, K0, K1 ----
    {
        int plane = tid >> 8, ci = tid & 255, row = ci >> 3, seg = ci & 7;
        const uint32_t* src = (plane ? g_ql : g_qh) +
            (size_t)(r0 + row) * 2048 + bh * 32 + seg * 4;
        cp16(smb + (uint32_t)((plane ? QL_W : QH_W) + row * 36 + seg * 4) * 4, src);
        cp_commit();
    }
    issueK(0);
    issueK(1);

    cp_wait<2>();
    __syncthreads();
    uint32_t qah[4][4], qal[4][4];
    #pragma unroll
    for (int ks = 0; ks < 4; ks++) {
        ldsm_x4(qah[ks], smb + (uint32_t)(QH_W + qfb + ks * 8) * 4);
        ldsm_x4(qal[ks], smb + (uint32_t)(QL_W + qfb + ks * 8) * 4);
    }

    // ---- scores into registers (64 floats/thread) ----
    float sv[64];
    #pragma unroll
    for (int j = 0; j < 64; j++) sv[j] = 0.0f;

    const int rowg = r0 + m0 + g;

    #pragma unroll
    for (int it = 0; it < 8; it++) {
        if (it == 7) cp_wait<0>(); else cp_wait<1>();
        __syncthreads();
        const uint32_t KHa = smb + (uint32_t)((it & 1) * 9216 + kfb) * 4;
        const uint32_t KLa = KHa + 4608 * 4;
        float* s = sv + it * 8;

        #pragma unroll
        for (int ks = 0; ks < 4; ks++) {
            uint32_t bhf[4], blf[4];
            ldsm_x4(bhf, KHa + ks * 32);
            ldsm_x4(blf, KLa + ks * 32);
            mma_bf16(s,     qah[ks], bhf);
            mma_bf16(s,     qah[ks], blf);
            mma_bf16(s,     qal[ks], bhf);
            mma_bf16(s + 4, qah[ks], bhf + 2);
            mma_bf16(s + 4, qah[ks], blf + 2);
            mma_bf16(s + 4, qal[ks], bhf + 2);
        }
        {
            int c0 = it * 128 + n0 + 2 * t;
            int c1 = c0 + 8;
            float2 b00 = *(const float2*)(bsrc + (size_t)rowg * 1024 + c0);
            float2 b01 = *(const float2*)(bsrc + (size_t)(rowg + 8) * 1024 + c0);
            float2 b10 = *(const float2*)(bsrc + (size_t)rowg * 1024 + c1);
            float2 b11 = *(const float2*)(bsrc + (size_t)(rowg + 8) * 1024 + c1);
            s[0] += b00.x; s[1] += b00.y;
            s[2] += b01.x; s[3] += b01.y;
            s[4] += b10.x; s[5] += b10.y;
            s[6] += b11.x; s[7] += b11.y;
        }
        __syncthreads();
        if (it < 6) issueK(it + 2);
    }

    // ---- V pipeline prologue (overlaps softmax) ----
    issueV(0);
    issueV(1);

    // ---- softmax: quad shuffle + cross-warp smem reduce ----
    float mg = -3.0e38f, mg8 = -3.0e38f;
    #pragma unroll
    for (int it = 0; it < 8; it++) {
        float* s = sv + it * 8;
        mg  = fmaxf(mg,  fmaxf(fmaxf(s[0], s[1]), fmaxf(s[4], s[5])));
        mg8 = fmaxf(mg8, fmaxf(fmaxf(s[2], s[3]), fmaxf(s[6], s[7])));
    }
    mg  = fmaxf(mg,  __shfl_xor_sync(0xffffffffu, mg, 1));
    mg  = fmaxf(mg,  __shfl_xor_sync(0xffffffffu, mg, 2));
    mg8 = fmaxf(mg8, __shfl_xor_sync(0xffffffffu, mg8, 1));
    mg8 = fmaxf(mg8, __shfl_xor_sync(0xffffffffu, mg8, 2));
    if (t == 0) {
        scrM[(m0 + g) * 8 + wn]     = mg;
        scrM[(m0 + g + 8) * 8 + wn] = mg8;
    }
    __syncthreads();
    float Mg = -3.0e38f, Mg8 = -3.0e38f;
    #pragma unroll
    for (int k = 0; k < 8; k++) {
        Mg  = fmaxf(Mg,  scrM[(m0 + g) * 8 + k]);
        Mg8 = fmaxf(Mg8, scrM[(m0 + g + 8) * 8 + k]);
    }
    float sg = 0.0f, sg8 = 0.0f;
    #pragma unroll
    for (int it = 0; it < 8; it++) {
        float* s = sv + it * 8;
        s[0] = __expf(s[0] - Mg);  s[1] = __expf(s[1] - Mg);
        s[4] = __expf(s[4] - Mg);  s[5] = __expf(s[5] - Mg);
        s[2] = __expf(s[2] - Mg8); s[3] = __expf(s[3] - Mg8);
        s[6] = __expf(s[6] - Mg8); s[7] = __expf(s[7] - Mg8);
        sg  += s[0] + s[1] + s[4] + s[5];
        sg8 += s[2] + s[3] + s[6] + s[7];
    }
    sg  += __shfl_xor_sync(0xffffffffu, sg, 1);
    sg  += __shfl_xor_sync(0xffffffffu, sg, 2);
    sg8 += __shfl_xor_sync(0xffffffffu, sg8, 1);
    sg8 += __shfl_xor_sync(0xffffffffu, sg8, 2);
    if (t == 0) {
        scrS[(m0 + g) * 8 + wn]     = sg;
        scrS[(m0 + g + 8) * 8 + wn] = sg8;
    }
    __syncthreads();
    float Sg = 0.0f, Sg8 = 0.0f;
    #pragma unroll
    for (int k = 0; k < 8; k++) {
        Sg  += scrS[(m0 + g) * 8 + k];
        Sg8 += scrS[(m0 + g + 8) * 8 + k];
    }
    const float invg = 1.0f / Sg, invg8 = 1.0f / Sg8;

    // ---- AV loop: per-tile P scale + weights-store + pack + MMA ----
    float* wr0 = wrow_base + (size_t)rowg * 1024;
    float* wr8 = wrow_base + (size_t)(rowg + 8) * 1024;

    float oacc[8][4];
    #pragma unroll
    for (int i = 0; i < 8; i++)
        #pragma unroll
        for (int j = 0; j < 4; j++) oacc[i][j] = 0.0f;

    #pragma unroll
    for (int it = 0; it < 8; it++) {
        if (it == 7) cp_wait<0>(); else cp_wait<1>();
        __syncthreads();
        const uint32_t VHa = smb + (uint32_t)((it & 1) * 8704 + vfb) * 4;
        const uint32_t VLa = VHa + 4352 * 4;

        float* s = sv + it * 8;
        float p0 = s[0] * invg,  p1 = s[1] * invg;
        float p2 = s[2] * invg8, p3 = s[3] * invg8;
        float p4 = s[4] * invg,  p5 = s[5] * invg;
        float p6 = s[6] * invg8, p7 = s[7] * invg8;
        int c0 = it * 128 + n0 + 2 * t;
        *(float2*)&wr0[c0]     = make_float2(p0, p1);
        *(float2*)&wr8[c0]     = make_float2(p2, p3);
        *(float2*)&wr0[c0 + 8] = make_float2(p4, p5);
        *(float2*)&wr8[c0 + 8] = make_float2(p6, p7);
        uint32_t pah[4], pal[4];
        split2(p0, p1, pah[0], pal[0]);
        split2(p2, p3, pah[1], pal[1]);
        split2(p4, p5, pah[2], pal[2]);
        split2(p6, p7, pah[3], pal[3]);

        #pragma unroll
        for (int ntp = 0; ntp < 8; ntp += 2) {
            uint32_t vhf[4], vlf[4];
            ldsm_x4(vhf, VHa + ntp * 2176);     // ntp*8 rows * 68 words * 4 B
            ldsm_x4(vlf, VLa + ntp * 2176);
            mma_bf16(oacc[ntp],     pah, vhf);
            mma_bf16(oacc[ntp],     pah, vlf);
            mma_bf16(oacc[ntp],     pal, vhf);
            mma_bf16(oacc[ntp + 1], pah, vhf + 2);
            mma_bf16(oacc[ntp + 1], pah, vlf + 2);
            mma_bf16(oacc[ntp + 1], pal, vhf + 2);
        }
        __syncthreads();
        if (it < 6) issueV(it + 2);
    }

    // ---- tree-reduce 8 wn-partials (overlay on KV region) ----
    __syncthreads();
    float* red = sm + KV_W;
    auto stPart = [&](int b) {
        int base = b * 2176 + wm * 1088;
        #pragma unroll
        for (int nt = 0; nt < 8; nt++) {
            *(float2*)&red[base + g * 66 + nt * 8 + 2 * t] =
                make_float2(oacc[nt][0], oacc[nt][1]);
            *(float2*)&red[base + (g + 8) * 66 + nt * 8 + 2 * t] =
                make_float2(oacc[nt][2], oacc[nt][3]);
        }
    };
    auto addPart = [&](int b) {
        int base = b * 2176 + wm * 1088;
        #pragma unroll
        for (int nt = 0; nt < 8; nt++) {
            float2 p0 = *(float2*)&red[base + g * 66 + nt * 8 + 2 * t];
            float2 p1 = *(float2*)&red[base + (g + 8) * 66 + nt * 8 + 2 * t];
            oacc[nt][0] += p0.x; oacc[nt][1] += p0.y;
            oacc[nt][2] += p1.x; oacc[nt][3] += p1.y;
        }
    };
    if (wn >= 4) stPart(wn - 4);
    __syncthreads();
    if (wn < 4) addPart(wn);
    __syncthreads();
    if (wn == 2 || wn == 3) stPart(wn - 2);
    __syncthreads();
    if (wn < 2) addPart(wn);
    __syncthreads();
    if (wn == 1) stPart(0);
    __syncthreads();
    if (wn == 0) {
        addPart(0);
        size_t ob = (size_t)(bh >> 4) * Nn * Ee + (size_t)(bh & 15) * 64;
        #pragma unroll
        for (int nt = 0; nt < 8; nt++) {
            int col = nt * 8 + 2 * t;
            *(float2*)&out_attn[ob + (size_t)rowg * Ee + col] =
                make_float2(oacc[nt][0], oacc[nt][1]);
            *(float2*)&out_attn[ob + (size_t)(rowg + 8) * Ee + col] =
                make_float2(oacc[nt][2], oacc[nt][3]);
        }
    }
}

// ---------------------------------------------------------------------------
extern "C" void kernel_launch(void* const* d_in, const int* in_sizes, int n_in,
                              void* d_out, int out_size) {
    const float* query = (const float*)d_in[0];
    const float* key_  = (const float*)d_in[1];
    const float* value = (const float*)d_in[2];
    const float* ab    = (const float*)d_in[3];
    const float* Wq    = (const float*)d_in[4];
    const float* bq    = (const float*)d_in[5];
    const float* Wk    = (const float*)d_in[6];
    const float* bk    = (const float*)d_in[7];
    const float* Wv    = (const float*)d_in[8];
    const float* bv    = (const float*)d_in[9];

    float* out = (float*)d_out;
    const long long attn_elems = (long long)Bc * Nn * Ee;
    const long long w_elems    = (long long)BHn * Nn * Nn;
    float* attn_out = out;
    float* w_out = nullptr;
    if ((long long)out_size >= attn_elems + w_elems) w_out = out + attn_elems;

    {
        dim3 grid(4096, 6);
        pack_kernel<<<grid, 256>>>(query, key_, value, Wq, Wk, Wv);
    }
    {
        cudaFuncSetAttribute(proj_mma_kernel, cudaFuncAttributeMaxDynamicSharedMemorySize,
                             PROJ_SMEM_BYTES);
        dim3 grid(Mtot / 128, Ee / 128, 3);
        proj_mma_kernel<<<grid, 256, PROJ_SMEM_BYTES>>>(bq, bk, bv);
    }
    {
        dim3 grid(8, 64);
        vt_kernel<<<grid, 256>>>();
    }
    {
        cudaFuncSetAttribute(attn_mma_kernel, cudaFuncAttributeMaxDynamicSharedMemorySize,
                             ATTN_SMEM_BYTES);
        dim3 grid(Nn / 32, BHn);
        attn_mma_kernel<<<grid, 512, ATTN_SMEM_BYTES>>>(ab, attn_out, w_out);
    }
}

// round 13
// speedup vs baseline: 1.5615x; 1.0071x over previous
#include <cuda_runtime.h>
#include <cstdint>

#define Bc   4
#define Nn   1024
#define Ee   1024
#define BHn  64
#define Mtot 4096   // B*N

// Projected Q/K as separate hi/lo bf16x2 planes (pair p covers cols 2p,2p+1).
__device__ uint32_t g_qh[Mtot * 512];
__device__ uint32_t g_ql[Mtot * 512];
__device__ uint32_t g_kh[Mtot * 512];
__device__ uint32_t g_kl[Mtot * 512];
__device__ float    g_v [Mtot * Ee];
// V^T packed planes: [bh][d][cpair]  (64 x 64 x 512)
__device__ uint32_t g_vth[64 * 64 * 512];
__device__ uint32_t g_vtl[64 * 64 * 512];
// Packed GEMM input planes: [z][...]
__device__ uint32_t g_pxh[3][Mtot * 512];
__device__ uint32_t g_pxl[3][Mtot * 512];
__device__ uint32_t g_pwh[3][1024 * 512];
__device__ uint32_t g_pwl[3][1024 * 512];
// Fallback weights buffer if the harness output only holds attn.
__device__ float g_w[(size_t)BHn * Nn * Nn];

// ===========================================================================
// helpers
// ===========================================================================
static __device__ __forceinline__ uint32_t smem_u32(const void* p) {
    uint32_t a;
    asm("{ .reg .u64 t; cvta.to.shared.u64 t, %1; cvt.u32.u64 %0, t; }" : "=r"(a) : "l"(p));
    return a;
}
static __device__ __forceinline__ uint32_t pack_bf16(float x0, float x1) {
    uint32_t r;
    asm("cvt.rn.bf16x2.f32 %0, %1, %2;" : "=r"(r) : "f"(x1), "f"(x0));
    return r;
}
static __device__ __forceinline__ void split2(float x0, float x1, uint32_t& h, uint32_t& l) {
    h = pack_bf16(x0, x1);
    float h0 = __uint_as_float(h << 16);
    float h1 = __uint_as_float(h & 0xFFFF0000u);
    l = pack_bf16(x0 - h0, x1 - h1);
}
static __device__ __forceinline__ void mma_bf16(float* c, const uint32_t* a, const uint32_t* b) {
    asm volatile(
        "mma.sync.aligned.m16n8k16.row.col.f32.bf16.bf16.f32 "
        "{%0,%1,%2,%3}, {%4,%5,%6,%7}, {%8,%9}, {%0,%1,%2,%3};"
        : "+f"(c[0]), "+f"(c[1]), "+f"(c[2]), "+f"(c[3])
        : "r"(a[0]), "r"(a[1]), "r"(a[2]), "r"(a[3]), "r"(b[0]), "r"(b[1]));
}
static __device__ __forceinline__ void ldsm_x4(uint32_t* r, uint32_t addr) {
    asm volatile("ldmatrix.sync.aligned.m8n8.x4.shared.b16 {%0,%1,%2,%3}, [%4];"
                 : "=r"(r[0]), "=r"(r[1]), "=r"(r[2]), "=r"(r[3]) : "r"(addr));
}
static __device__ __forceinline__ void cp16(uint32_t dst, const void* src) {
    asm volatile("cp.async.cg.shared.global [%0], [%1], 16;" :: "r"(dst), "l"(src));
}
static __device__ __forceinline__ void cp_commit() {
    asm volatile("cp.async.commit_group;" ::: "memory");
}
template<int N> static __device__ __forceinline__ void cp_wait() {
    asm volatile("cp.async.wait_group %0;" :: "n"(N) : "memory");
}

// ===========================================================================
// Pack kernel: fp32 -> separate hi/lo plane pairs for proj inputs.
// ===========================================================================
__global__ __launch_bounds__(256) void pack_kernel(
    const float* __restrict__ xq, const float* __restrict__ xk, const float* __restrict__ xv,
    const float* __restrict__ wq, const float* __restrict__ wk, const float* __restrict__ wv)
{
    const int z = blockIdx.y;
    const float* src; uint32_t* dh; uint32_t* dl; int nf4;
    switch (z) {
        case 0: src = xq; dh = g_pxh[0]; dl = g_pxl[0]; nf4 = Mtot * 256; break;
        case 1: src = xk; dh = g_pxh[1]; dl = g_pxl[1]; nf4 = Mtot * 256; break;
        case 2: src = xv; dh = g_pxh[2]; dl = g_pxl[2]; nf4 = Mtot * 256; break;
        case 3: src = wq; dh = g_pwh[0]; dl = g_pwl[0]; nf4 = 1024 * 256; break;
        case 4: src = wk; dh = g_pwh[1]; dl = g_pwl[1]; nf4 = 1024 * 256; break;
        default: src = wv; dh = g_pwh[2]; dl = g_pwl[2]; nf4 = 1024 * 256; break;
    }
    int i = blockIdx.x * 256 + threadIdx.x;
    if (i >= nf4) return;
    float4 v = *(const float4*)(src + (size_t)i * 4);
    uint32_t h0, l0, h1, l1;
    split2(v.x, v.y, h0, l0);
    split2(v.z, v.w, h1, l1);
    *(uint2*)&dh[2 * i] = make_uint2(h0, h1);
    *(uint2*)&dl[2 * i] = make_uint2(l0, l1);
}

// ===========================================================================
// Projection GEMM: C = X @ W^T + b, cp.async double-buffered, 2 CTAs/SM.
// Fragment loads via ldmatrix.x4 (stride 20: banks 20r mod 32 distinct).
// ===========================================================================
#define PSP 20
#define PSTAGE (4 * 128 * PSP)                      // 10240 words
#define PROJ_SMEM_BYTES ((2 * PSTAGE + 128) * 4)    // 82432

__global__ __launch_bounds__(256, 2) void proj_mma_kernel(
    const float* __restrict__ bq, const float* __restrict__ bk, const float* __restrict__ bv)
{
    extern __shared__ uint32_t psm[];
    float* bsm = (float*)(psm + 2 * PSTAGE);
    const uint32_t smb = smem_u32(psm);

    const int z = blockIdx.z;
    const uint32_t* xh = g_pxh[z]; const uint32_t* xl = g_pxl[z];
    const uint32_t* wh = g_pwh[z]; const uint32_t* wl = g_pwl[z];
    const float* bias = (z == 0) ? bq : (z == 1) ? bk : bv;

    const int tid = threadIdx.x;
    const int w = tid >> 5, lane = tid & 31;
    const int g = lane >> 2, t = lane & 3;
    const int l8 = lane & 7;
    const int bm = blockIdx.x * 128, bn = blockIdx.y * 128;
    const int wm = w >> 2, wn = w & 3;

    if (tid < 128) bsm[tid] = bias[bn + tid];

    // ldmatrix lane bases (word offsets within a plane)
    const int pafb = (wm * 64 + ((lane >> 3) & 1) * 8 + l8) * PSP + ((lane >> 4) & 1) * 4;
    const int pbfb = (wn * 32 + ((lane >> 4) & 1) * 8 + l8) * PSP + ((lane >> 3) & 1) * 4;

    auto issueP = [&](int kc) {
        int st = kc & 1;
        #pragma unroll
        for (int s = 0; s < 8; s++) {
            int idx = tid + 256 * s;          // 0..2047
            int plane = idx >> 9;
            int row = (idx >> 2) & 127;
            int seg = idx & 3;
            const uint32_t* src;
            if (plane == 0)      src = xh + (size_t)(bm + row) * 512 + kc * 16 + seg * 4;
            else if (plane == 1) src = xl + (size_t)(bm + row) * 512 + kc * 16 + seg * 4;
            else if (plane == 2) src = wh + (size_t)(bn + row) * 512 + kc * 16 + seg * 4;
            else                 src = wl + (size_t)(bn + row) * 512 + kc * 16 + seg * 4;
            cp16(smb + (uint32_t)(st * PSTAGE + plane * 128 * PSP + row * PSP + seg * 4) * 4, src);
        }
        cp_commit();
    };

    issueP(0);
    issueP(1);

    float acc[4][4][4];
    #pragma unroll
    for (int i = 0; i < 4; i++)
        #pragma unroll
        for (int j = 0; j < 4; j++)
            #pragma unroll
            for (int k = 0; k < 4; k++) acc[i][j][k] = 0.0f;

    #pragma unroll 1
    for (int kc = 0; kc < 32; kc++) {
        if (kc == 31) cp_wait<0>(); else cp_wait<1>();
        __syncthreads();
        const uint32_t stA = smb + (uint32_t)((kc & 1) * PSTAGE) * 4;
        const uint32_t XHa = stA;
        const uint32_t XLa = stA + (uint32_t)(128 * PSP) * 4;
        const uint32_t WHa = stA + (uint32_t)(2 * 128 * PSP) * 4;
        const uint32_t WLa = stA + (uint32_t)(3 * 128 * PSP) * 4;

        #pragma unroll
        for (int ks = 0; ks < 2; ks++) {
            uint32_t wbh[8], wbl[8];
            ldsm_x4(wbh,     WHa + (uint32_t)(pbfb + ks * 8) * 4);
            ldsm_x4(wbh + 4, WHa + (uint32_t)(pbfb + 16 * PSP + ks * 8) * 4);
            ldsm_x4(wbl,     WLa + (uint32_t)(pbfb + ks * 8) * 4);
            ldsm_x4(wbl + 4, WLa + (uint32_t)(pbfb + 16 * PSP + ks * 8) * 4);
            #pragma unroll
            for (int mt = 0; mt < 4; mt++) {
                uint32_t ah[4], al[4];
                ldsm_x4(ah, XHa + (uint32_t)(pafb + mt * 16 * PSP + ks * 8) * 4);
                ldsm_x4(al, XLa + (uint32_t)(pafb + mt * 16 * PSP + ks * 8) * 4);
                #pragma unroll
                for (int nt = 0; nt < 4; nt++) {
                    mma_bf16(acc[mt][nt], ah, &wbh[nt * 2]);
                    mma_bf16(acc[mt][nt], ah, &wbl[nt * 2]);
                    mma_bf16(acc[mt][nt], al, &wbh[nt * 2]);
                }
            }
        }
        __syncthreads();
        if (kc < 30) issueP(kc + 2);
    }

    #pragma unroll
    for (int mt = 0; mt < 4; mt++) {
        int row = wm * 64 + mt * 16 + g;
        #pragma unroll
        for (int nt = 0; nt < 4; nt++) {
            int col = wn * 32 + nt * 8 + 2 * t;
            float bx = bsm[col], by = bsm[col + 1];
            float c00 = acc[mt][nt][0] + bx, c01 = acc[mt][nt][1] + by;
            float c10 = acc[mt][nt][2] + bx, c11 = acc[mt][nt][3] + by;
            if (z < 2) {
                uint32_t* dh = (z == 0) ? g_qh : g_kh;
                uint32_t* dl = (z == 0) ? g_ql : g_kl;
                size_t p0 = (size_t)(bm + row) * 512 + ((bn + col) >> 1);
                size_t p1 = (size_t)(bm + row + 8) * 512 + ((bn + col) >> 1);
                uint32_t h, l;
                split2(c00, c01, h, l);
                dh[p0] = h; dl[p0] = l;
                split2(c10, c11, h, l);
                dh[p1] = h; dl[p1] = l;
            } else {
                *(float2*)(g_v + (size_t)(bm + row) * 1024 + bn + col) = make_float2(c00, c01);
                *(float2*)(g_v + (size_t)(bm + row + 8) * 1024 + bn + col) = make_float2(c10, c11);
            }
        }
    }
}

// ===========================================================================
// V transpose+pack: g_v (natural) -> g_vth/g_vtl [bh][d][cpair].
// ===========================================================================
__global__ __launch_bounds__(256) void vt_kernel()
{
    __shared__ uint32_t sh[64 * 65], sl[64 * 65];
    const int bh = blockIdx.y, ct = blockIdx.x, tid = threadIdx.x;

    #pragma unroll
    for (int s = 0; s < 16; s++) {
        int idx = tid + 256 * s;
        int d = idx & 63, cp = idx >> 6;
        const float* p = g_v + (size_t)(ct * 128 + 2 * cp) * 4096 + bh * 64 + d;
        float x0 = p[0], x1 = p[4096];
        uint32_t h, l;
        split2(x0, x1, h, l);
        sh[cp * 65 + d] = h;
        sl[cp * 65 + d] = l;
    }
    __syncthreads();
    #pragma unroll
    for (int s = 0; s < 16; s++) {
        int idx = tid + 256 * s;
        int cp = idx & 63, d = idx >> 6;
        size_t o = ((size_t)(bh * 64 + d) << 9) + ct * 64 + cp;
        g_vth[o] = sh[cp * 65 + d];
        g_vtl[o] = sl[cp * 65 + d];
    }
}

// ===========================================================================
// Attention: register-resident scores; ldmatrix frags; bias via cp.async.
// ===========================================================================
#define KV_W   0
#define QH_W   18432
#define QL_W   (QH_W + 1152)
#define SCRM_W (QL_W + 1152)
#define SCRS_W (SCRM_W + 256)
#define BIA_W  (SCRS_W + 256)           // 21256; 2 buffers of 32x132
#define ATTN_SMEM_WORDS (BIA_W + 2 * 4224)   // 29704
#define ATTN_SMEM_BYTES (ATTN_SMEM_WORDS * 4) // 118816

__global__ __launch_bounds__(512, 1) void attn_mma_kernel(
    const float* __restrict__ bias, float* __restrict__ out_attn, float* __restrict__ w_out)
{
    extern __shared__ float sm[];
    float* scrM = sm + SCRM_W;
    float* scrS = sm + SCRS_W;
    const uint32_t smb = smem_u32(sm);

    const int tid = threadIdx.x;
    const int w = tid >> 5, lane = tid & 31;
    const int g = lane >> 2, t = lane & 3;
    const int l8 = lane & 7;
    const int wm = w >> 3, wn = w & 7;
    const int m0 = wm * 16, n0 = wn * 16;
    const int bh = blockIdx.y;
    const int r0 = blockIdx.x * 32;

    const float* bsrc = bias + (size_t)(bh & 3) * Nn * Nn;
    float* wbase = (w_out != nullptr) ? w_out : g_w;
    float* wrow_base = wbase + (size_t)bh * Nn * Nn;

    // ldmatrix lane bases (word offsets)
    const int qfb = (m0 + ((lane >> 3) & 1) * 8 + l8) * 36 + ((lane >> 4) & 1) * 4;
    const int kfb = (n0 + ((lane >> 4) & 1) * 8 + l8) * 36 + ((lane >> 3) & 1) * 4;
    const int vfb = (((lane >> 4) & 1) * 8 + l8) * 68 + wn * 8 + ((lane >> 3) & 1) * 4;

    // K tile + bias tile in ONE commit group (wait logic unchanged)
    auto issueK = [&](int it) {
        int b = it & 1;
        #pragma unroll
        for (int s = 0; s < 4; s++) {
            int idx = tid + 512 * s;
            int plane = idx >> 10;
            int row = (idx >> 3) & 127;
            int seg = idx & 7;
            const uint32_t* src = (plane ? g_kl : g_kh) +
                (size_t)(it * 128 + row) * 2048 + bh * 32 + seg * 4;
            cp16(smb + (uint32_t)(KV_W + b * 9216 + plane * 4608 + row * 36 + seg * 4) * 4, src);
        }
        #pragma unroll
        for (int s = 0; s < 2; s++) {
            int idx = tid + 512 * s;          // 0..1023
            int row = idx >> 5;               // 0..31
            int seg = idx & 31;               // 4 floats each
            const float* src = bsrc + (size_t)(r0 + row) * 1024 + it * 128 + seg * 4;
            cp16(smb + (uint32_t)(BIA_W + b * 4224 + row * 132 + seg * 4) * 4, src);
        }
        cp_commit();
    };
    auto issueV = [&](int it) {
        int b = it & 1;
        #pragma unroll
        for (int s = 0; s < 4; s++) {
            int idx = tid + 512 * s;
            int plane = idx >> 10;
            int row = (idx >> 4) & 63;
            int seg = idx & 15;
            const uint32_t* src = (plane ? g_vtl : g_vth) +
                (((size_t)(bh * 64 + row)) << 9) + it * 64 + seg * 4;
            cp16(smb + (uint32_t)(KV_W + b * 8704 + plane * 4352 + row * 68 + seg * 4) * 4, src);
        }
        cp_commit();
    };

    // ---- prologue: Q, K0+B0, K1+B1 ----
    {
        int plane = tid >> 8, ci = tid & 255, row = ci >> 3, seg = ci & 7;
        const uint32_t* src = (plane ? g_ql : g_qh) +
            (size_t)(r0 + row) * 2048 + bh * 32 + seg * 4;
        cp16(smb + (uint32_t)((plane ? QL_W : QH_W) + row * 36 + seg * 4) * 4, src);
        cp_commit();
    }
    issueK(0);
    issueK(1);

    cp_wait<2>();
    __syncthreads();
    uint32_t qah[4][4], qal[4][4];
    #pragma unroll
    for (int ks = 0; ks < 4; ks++) {
        ldsm_x4(qah[ks], smb + (uint32_t)(QH_W + qfb + ks * 8) * 4);
        ldsm_x4(qal[ks], smb + (uint32_t)(QL_W + qfb + ks * 8) * 4);
    }

    // ---- scores into registers (64 floats/thread) ----
    float sv[64];
    #pragma unroll
    for (int j = 0; j < 64; j++) sv[j] = 0.0f;

    const int rowg = r0 + m0 + g;

    #pragma unroll
    for (int it = 0; it < 8; it++) {
        if (it == 7) cp_wait<0>(); else cp_wait<1>();
        __syncthreads();
        const uint32_t KHa = smb + (uint32_t)((it & 1) * 9216 + kfb) * 4;
        const uint32_t KLa = KHa + 4608 * 4;
        const float* Bb = sm + BIA_W + (it & 1) * 4224;
        float* s = sv + it * 8;

        #pragma unroll
        for (int ks = 0; ks < 4; ks++) {
            uint32_t bhf[4], blf[4];
            ldsm_x4(bhf, KHa + ks * 32);
            ldsm_x4(blf, KLa + ks * 32);
            mma_bf16(s,     qah[ks], bhf);
            mma_bf16(s,     qah[ks], blf);
            mma_bf16(s,     qal[ks], bhf);
            mma_bf16(s + 4, qah[ks], bhf + 2);
            mma_bf16(s + 4, qah[ks], blf + 2);
            mma_bf16(s + 4, qal[ks], bhf + 2);
        }
        {
            int c0l = n0 + 2 * t;
            float2 b00 = *(const float2*)&Bb[(m0 + g) * 132 + c0l];
            float2 b01 = *(const float2*)&Bb[(m0 + g + 8) * 132 + c0l];
            float2 b10 = *(const float2*)&Bb[(m0 + g) * 132 + c0l + 8];
            float2 b11 = *(const float2*)&Bb[(m0 + g + 8) * 132 + c0l + 8];
            s[0] += b00.x; s[1] += b00.y;
            s[2] += b01.x; s[3] += b01.y;
            s[4] += b10.x; s[5] += b10.y;
            s[6] += b11.x; s[7] += b11.y;
        }
        __syncthreads();
        if (it < 6) issueK(it + 2);
    }

    // ---- V pipeline prologue (overlaps softmax) ----
    issueV(0);
    issueV(1);

    // ---- softmax: quad shuffle + cross-warp smem reduce ----
    float mg = -3.0e38f, mg8 = -3.0e38f;
    #pragma unroll
    for (int it = 0; it < 8; it++) {
        float* s = sv + it * 8;
        mg  = fmaxf(mg,  fmaxf(fmaxf(s[0], s[1]), fmaxf(s[4], s[5])));
        mg8 = fmaxf(mg8, fmaxf(fmaxf(s[2], s[3]), fmaxf(s[6], s[7])));
    }
    mg  = fmaxf(mg,  __shfl_xor_sync(0xffffffffu, mg, 1));
    mg  = fmaxf(mg,  __shfl_xor_sync(0xffffffffu, mg, 2));
    mg8 = fmaxf(mg8, __shfl_xor_sync(0xffffffffu, mg8, 1));
    mg8 = fmaxf(mg8, __shfl_xor_sync(0xffffffffu, mg8, 2));
    if (t == 0) {
        scrM[(m0 + g) * 8 + wn]     = mg;
        scrM[(m0 + g + 8) * 8 + wn] = mg8;
    }
    __syncthreads();
    float Mg = -3.0e38f, Mg8 = -3.0e38f;
    #pragma unroll
    for (int k = 0; k < 8; k++) {
        Mg  = fmaxf(Mg,  scrM[(m0 + g) * 8 + k]);
        Mg8 = fmaxf(Mg8, scrM[(m0 + g + 8) * 8 + k]);
    }
    float sg = 0.0f, sg8 = 0.0f;
    #pragma unroll
    for (int it = 0; it < 8; it++) {
        float* s = sv + it * 8;
        s[0] = __expf(s[0] - Mg);  s[1] = __expf(s[1] - Mg);
        s[4] = __expf(s[4] - Mg);  s[5] = __expf(s[5] - Mg);
        s[2] = __expf(s[2] - Mg8); s[3] = __expf(s[3] - Mg8);
        s[6] = __expf(s[6] - Mg8); s[7] = __expf(s[7] - Mg8);
        sg  += s[0] + s[1] + s[4] + s[5];
        sg8 += s[2] + s[3] + s[6] + s[7];
    }
    sg  += __shfl_xor_sync(0xffffffffu, sg, 1);
    sg  += __shfl_xor_sync(0xffffffffu, sg, 2);
    sg8 += __shfl_xor_sync(0xffffffffu, sg8, 1);
    sg8 += __shfl_xor_sync(0xffffffffu, sg8, 2);
    if (t == 0) {
        scrS[(m0 + g) * 8 + wn]     = sg;
        scrS[(m0 + g + 8) * 8 + wn] = sg8;
    }
    __syncthreads();
    float Sg = 0.0f, Sg8 = 0.0f;
    #pragma unroll
    for (int k = 0; k < 8; k++) {
        Sg  += scrS[(m0 + g) * 8 + k];
        Sg8 += scrS[(m0 + g + 8) * 8 + k];
    }
    const float invg = 1.0f / Sg, invg8 = 1.0f / Sg8;

    // ---- AV loop: per-tile P scale + weights-store + pack + MMA ----
    float* wr0 = wrow_base + (size_t)rowg * 1024;
    float* wr8 = wrow_base + (size_t)(rowg + 8) * 1024;

    float oacc[8][4];
    #pragma unroll
    for (int i = 0; i < 8; i++)
        #pragma unroll
        for (int j = 0; j < 4; j++) oacc[i][j] = 0.0f;

    #pragma unroll
    for (int it = 0; it < 8; it++) {
        if (it == 7) cp_wait<0>(); else cp_wait<1>();
        __syncthreads();
        const uint32_t VHa = smb + (uint32_t)((it & 1) * 8704 + vfb) * 4;
        const uint32_t VLa = VHa + 4352 * 4;

        float* s = sv + it * 8;
        float p0 = s[0] * invg,  p1 = s[1] * invg;
        float p2 = s[2] * invg8, p3 = s[3] * invg8;
        float p4 = s[4] * invg,  p5 = s[5] * invg;
        float p6 = s[6] * invg8, p7 = s[7] * invg8;
        int c0 = it * 128 + n0 + 2 * t;
        *(float2*)&wr0[c0]     = make_float2(p0, p1);
        *(float2*)&wr8[c0]     = make_float2(p2, p3);
        *(float2*)&wr0[c0 + 8] = make_float2(p4, p5);
        *(float2*)&wr8[c0 + 8] = make_float2(p6, p7);
        uint32_t pah[4], pal[4];
        split2(p0, p1, pah[0], pal[0]);
        split2(p2, p3, pah[1], pal[1]);
        split2(p4, p5, pah[2], pal[2]);
        split2(p6, p7, pah[3], pal[3]);

        #pragma unroll
        for (int ntp = 0; ntp < 8; ntp += 2) {
            uint32_t vhf[4], vlf[4];
            ldsm_x4(vhf, VHa + ntp * 2176);
            ldsm_x4(vlf, VLa + ntp * 2176);
            mma_bf16(oacc[ntp],     pah, vhf);
            mma_bf16(oacc[ntp],     pah, vlf);
            mma_bf16(oacc[ntp],     pal, vhf);
            mma_bf16(oacc[ntp + 1], pah, vhf + 2);
            mma_bf16(oacc[ntp + 1], pah, vlf + 2);
            mma_bf16(oacc[ntp + 1], pal, vhf + 2);
        }
        __syncthreads();
        if (it < 6) issueV(it + 2);
    }

    // ---- tree-reduce 8 wn-partials (overlay on KV region) ----
    __syncthreads();
    float* red = sm + KV_W;
    auto stPart = [&](int b) {
        int base = b * 2176 + wm * 1088;
        #pragma unroll
        for (int nt = 0; nt < 8; nt++) {
            *(float2*)&red[base + g * 66 + nt * 8 + 2 * t] =
                make_float2(oacc[nt][0], oacc[nt][1]);
            *(float2*)&red[base + (g + 8) * 66 + nt * 8 + 2 * t] =
                make_float2(oacc[nt][2], oacc[nt][3]);
        }
    };
    auto addPart = [&](int b) {
        int base = b * 2176 + wm * 1088;
        #pragma unroll
        for (int nt = 0; nt < 8; nt++) {
            float2 p0 = *(float2*)&red[base + g * 66 + nt * 8 + 2 * t];
            float2 p1 = *(float2*)&red[base + (g + 8) * 66 + nt * 8 + 2 * t];
            oacc[nt][0] += p0.x; oacc[nt][1] += p0.y;
            oacc[nt][2] += p1.x; oacc[nt][3] += p1.y;
        }
    };
    if (wn >= 4) stPart(wn - 4);
    __syncthreads();
    if (wn < 4) addPart(wn);
    __syncthreads();
    if (wn == 2 || wn == 3) stPart(wn - 2);
    __syncthreads();
    if (wn < 2) addPart(wn);
    __syncthreads();
    if (wn == 1) stPart(0);
    __syncthreads();
    if (wn == 0) {
        addPart(0);
        size_t ob = (size_t)(bh >> 4) * Nn * Ee + (size_t)(bh & 15) * 64;
        #pragma unroll
        for (int nt = 0; nt < 8; nt++) {
            int col = nt * 8 + 2 * t;
            *(float2*)&out_attn[ob + (size_t)rowg * Ee + col] =
                make_float2(oacc[nt][0], oacc[nt][1]);
            *(float2*)&out_attn[ob + (size_t)(rowg + 8) * Ee + col] =
                make_float2(oacc[nt][2], oacc[nt][3]);
        }
    }
}

// ---------------------------------------------------------------------------
extern "C" void kernel_launch(void* const* d_in, const int* in_sizes, int n_in,
                              void* d_out, int out_size) {
    const float* query = (const float*)d_in[0];
    const float* key_  = (const float*)d_in[1];
    const float* value = (const float*)d_in[2];
    const float* ab    = (const float*)d_in[3];
    const float* Wq    = (const float*)d_in[4];
    const float* bq    = (const float*)d_in[5];
    const float* Wk    = (const float*)d_in[6];
    const float* bk    = (const float*)d_in[7];
    const float* Wv    = (const float*)d_in[8];
    const float* bv    = (const float*)d_in[9];

    float* out = (float*)d_out;
    const long long attn_elems = (long long)Bc * Nn * Ee;
    const long long w_elems    = (long long)BHn * Nn * Nn;
    float* attn_out = out;
    float* w_out = nullptr;
    if ((long long)out_size >= attn_elems + w_elems) w_out = out + attn_elems;

    {
        dim3 grid(4096, 6);
        pack_kernel<<<grid, 256>>>(query, key_, value, Wq, Wk, Wv);
    }
    {
        cudaFuncSetAttribute(proj_mma_kernel, cudaFuncAttributeMaxDynamicSharedMemorySize,
                             PROJ_SMEM_BYTES);
        dim3 grid(Mtot / 128, Ee / 128, 3);
        proj_mma_kernel<<<grid, 256, PROJ_SMEM_BYTES>>>(bq, bk, bv);
    }
    {
        dim3 grid(8, 64);
        vt_kernel<<<grid, 256>>>();
    }
    {
        cudaFuncSetAttribute(attn_mma_kernel, cudaFuncAttributeMaxDynamicSharedMemorySize,
                             ATTN_SMEM_BYTES);
        dim3 grid(Nn / 32, BHn);
        attn_mma_kernel<<<grid, 512, ATTN_SMEM_BYTES>>>(ab, attn_out, w_out);
    }
}

// round 14
// speedup vs baseline: 1.6124x; 1.0326x over previous
#include <cuda_runtime.h>
#include <cstdint>

#define Bc   4
#define Nn   1024
#define Ee   1024
#define BHn  64
#define Mtot 4096   // B*N

// Projected Q/K as separate hi/lo bf16x2 planes (pair p covers cols 2p,2p+1).
__device__ uint32_t g_qh[Mtot * 512];
__device__ uint32_t g_ql[Mtot * 512];
__device__ uint32_t g_kh[Mtot * 512];
__device__ uint32_t g_kl[Mtot * 512];
__device__ float    g_v [Mtot * Ee];
// V^T packed planes: [bh][d][cpair]  (64 x 64 x 512)
__device__ uint32_t g_vth[64 * 64 * 512];
__device__ uint32_t g_vtl[64 * 64 * 512];
// Packed GEMM input planes: [z][...]
__device__ uint32_t g_pxh[3][Mtot * 512];
__device__ uint32_t g_pxl[3][Mtot * 512];
__device__ uint32_t g_pwh[3][1024 * 512];
__device__ uint32_t g_pwl[3][1024 * 512];
// Fallback weights buffer if the harness output only holds attn.
__device__ float g_w[(size_t)BHn * Nn * Nn];

// ===========================================================================
// helpers
// ===========================================================================
static __device__ __forceinline__ uint32_t smem_u32(const void* p) {
    uint32_t a;
    asm("{ .reg .u64 t; cvta.to.shared.u64 t, %1; cvt.u32.u64 %0, t; }" : "=r"(a) : "l"(p));
    return a;
}
static __device__ __forceinline__ uint32_t pack_bf16(float x0, float x1) {
    uint32_t r;
    asm("cvt.rn.bf16x2.f32 %0, %1, %2;" : "=r"(r) : "f"(x1), "f"(x0));
    return r;
}
static __device__ __forceinline__ void split2(float x0, float x1, uint32_t& h, uint32_t& l) {
    h = pack_bf16(x0, x1);
    float h0 = __uint_as_float(h << 16);
    float h1 = __uint_as_float(h & 0xFFFF0000u);
    l = pack_bf16(x0 - h0, x1 - h1);
}
static __device__ __forceinline__ void mma_bf16(float* c, const uint32_t* a, const uint32_t* b) {
    asm volatile(
        "mma.sync.aligned.m16n8k16.row.col.f32.bf16.bf16.f32 "
        "{%0,%1,%2,%3}, {%4,%5,%6,%7}, {%8,%9}, {%0,%1,%2,%3};"
        : "+f"(c[0]), "+f"(c[1]), "+f"(c[2]), "+f"(c[3])
        : "r"(a[0]), "r"(a[1]), "r"(a[2]), "r"(a[3]), "r"(b[0]), "r"(b[1]));
}
static __device__ __forceinline__ void ldsm_x4(uint32_t* r, uint32_t addr) {
    asm volatile("ldmatrix.sync.aligned.m8n8.x4.shared.b16 {%0,%1,%2,%3}, [%4];"
                 : "=r"(r[0]), "=r"(r[1]), "=r"(r[2]), "=r"(r[3]) : "r"(addr));
}
static __device__ __forceinline__ void cp16(uint32_t dst, const void* src) {
    asm volatile("cp.async.cg.shared.global [%0], [%1], 16;" :: "r"(dst), "l"(src));
}
static __device__ __forceinline__ void cp_commit() {
    asm volatile("cp.async.commit_group;" ::: "memory");
}
template<int N> static __device__ __forceinline__ void cp_wait() {
    asm volatile("cp.async.wait_group %0;" :: "n"(N) : "memory");
}

// ===========================================================================
// Pack kernel: fp32 -> separate hi/lo plane pairs for proj inputs.
// ===========================================================================
__global__ __launch_bounds__(256) void pack_kernel(
    const float* __restrict__ xq, const float* __restrict__ xk, const float* __restrict__ xv,
    const float* __restrict__ wq, const float* __restrict__ wk, const float* __restrict__ wv)
{
    const int z = blockIdx.y;
    const float* src; uint32_t* dh; uint32_t* dl; int nf4;
    switch (z) {
        case 0: src = xq; dh = g_pxh[0]; dl = g_pxl[0]; nf4 = Mtot * 256; break;
        case 1: src = xk; dh = g_pxh[1]; dl = g_pxl[1]; nf4 = Mtot * 256; break;
        case 2: src = xv; dh = g_pxh[2]; dl = g_pxl[2]; nf4 = Mtot * 256; break;
        case 3: src = wq; dh = g_pwh[0]; dl = g_pwl[0]; nf4 = 1024 * 256; break;
        case 4: src = wk; dh = g_pwh[1]; dl = g_pwl[1]; nf4 = 1024 * 256; break;
        default: src = wv; dh = g_pwh[2]; dl = g_pwl[2]; nf4 = 1024 * 256; break;
    }
    int i = blockIdx.x * 256 + threadIdx.x;
    if (i >= nf4) return;
    float4 v = *(const float4*)(src + (size_t)i * 4);
    uint32_t h0, l0, h1, l1;
    split2(v.x, v.y, h0, l0);
    split2(v.z, v.w, h1, l1);
    *(uint2*)&dh[2 * i] = make_uint2(h0, h1);
    *(uint2*)&dl[2 * i] = make_uint2(l0, l1);
}

// ===========================================================================
// Projection GEMM: C = X @ W^T + b, cp.async double-buffered, 2 CTAs/SM.
// ===========================================================================
#define PSP 20
#define PSTAGE (4 * 128 * PSP)                      // 10240 words
#define PROJ_SMEM_BYTES ((2 * PSTAGE + 128) * 4)    // 82432

__global__ __launch_bounds__(256, 2) void proj_mma_kernel(
    const float* __restrict__ bq, const float* __restrict__ bk, const float* __restrict__ bv)
{
    extern __shared__ uint32_t psm[];
    float* bsm = (float*)(psm + 2 * PSTAGE);
    const uint32_t smb = smem_u32(psm);

    const int z = blockIdx.z;
    const uint32_t* xh = g_pxh[z]; const uint32_t* xl = g_pxl[z];
    const uint32_t* wh = g_pwh[z]; const uint32_t* wl = g_pwl[z];
    const float* bias = (z == 0) ? bq : (z == 1) ? bk : bv;

    const int tid = threadIdx.x;
    const int w = tid >> 5, lane = tid & 31;
    const int g = lane >> 2, t = lane & 3;
    const int l8 = lane & 7;
    const int bm = blockIdx.x * 128, bn = blockIdx.y * 128;
    const int wm = w >> 2, wn = w & 3;

    if (tid < 128) bsm[tid] = bias[bn + tid];

    const int pafb = (wm * 64 + ((lane >> 3) & 1) * 8 + l8) * PSP + ((lane >> 4) & 1) * 4;
    const int pbfb = (wn * 32 + ((lane >> 4) & 1) * 8 + l8) * PSP + ((lane >> 3) & 1) * 4;

    auto issueP = [&](int kc) {
        int st = kc & 1;
        #pragma unroll
        for (int s = 0; s < 8; s++) {
            int idx = tid + 256 * s;
            int plane = idx >> 9;
            int row = (idx >> 2) & 127;
            int seg = idx & 3;
            const uint32_t* src;
            if (plane == 0)      src = xh + (size_t)(bm + row) * 512 + kc * 16 + seg * 4;
            else if (plane == 1) src = xl + (size_t)(bm + row) * 512 + kc * 16 + seg * 4;
            else if (plane == 2) src = wh + (size_t)(bn + row) * 512 + kc * 16 + seg * 4;
            else                 src = wl + (size_t)(bn + row) * 512 + kc * 16 + seg * 4;
            cp16(smb + (uint32_t)(st * PSTAGE + plane * 128 * PSP + row * PSP + seg * 4) * 4, src);
        }
        cp_commit();
    };

    issueP(0);
    issueP(1);

    float acc[4][4][4];
    #pragma unroll
    for (int i = 0; i < 4; i++)
        #pragma unroll
        for (int j = 0; j < 4; j++)
            #pragma unroll
            for (int k = 0; k < 4; k++) acc[i][j][k] = 0.0f;

    #pragma unroll 1
    for (int kc = 0; kc < 32; kc++) {
        if (kc == 31) cp_wait<0>(); else cp_wait<1>();
        __syncthreads();
        const uint32_t stA = smb + (uint32_t)((kc & 1) * PSTAGE) * 4;
        const uint32_t XHa = stA;
        const uint32_t XLa = stA + (uint32_t)(128 * PSP) * 4;
        const uint32_t WHa = stA + (uint32_t)(2 * 128 * PSP) * 4;
        const uint32_t WLa = stA + (uint32_t)(3 * 128 * PSP) * 4;

        #pragma unroll
        for (int ks = 0; ks < 2; ks++) {
            uint32_t wbh[8], wbl[8];
            ldsm_x4(wbh,     WHa + (uint32_t)(pbfb + ks * 8) * 4);
            ldsm_x4(wbh + 4, WHa + (uint32_t)(pbfb + 16 * PSP + ks * 8) * 4);
            ldsm_x4(wbl,     WLa + (uint32_t)(pbfb + ks * 8) * 4);
            ldsm_x4(wbl + 4, WLa + (uint32_t)(pbfb + 16 * PSP + ks * 8) * 4);
            #pragma unroll
            for (int mt = 0; mt < 4; mt++) {
                uint32_t ah[4], al[4];
                ldsm_x4(ah, XHa + (uint32_t)(pafb + mt * 16 * PSP + ks * 8) * 4);
                ldsm_x4(al, XLa + (uint32_t)(pafb + mt * 16 * PSP + ks * 8) * 4);
                #pragma unroll
                for (int nt = 0; nt < 4; nt++) {
                    mma_bf16(acc[mt][nt], ah, &wbh[nt * 2]);
                    mma_bf16(acc[mt][nt], ah, &wbl[nt * 2]);
                    mma_bf16(acc[mt][nt], al, &wbh[nt * 2]);
                }
            }
        }
        __syncthreads();
        if (kc < 30) issueP(kc + 2);
    }

    #pragma unroll
    for (int mt = 0; mt < 4; mt++) {
        int row = wm * 64 + mt * 16 + g;
        #pragma unroll
        for (int nt = 0; nt < 4; nt++) {
            int col = wn * 32 + nt * 8 + 2 * t;
            float bx = bsm[col], by = bsm[col + 1];
            float c00 = acc[mt][nt][0] + bx, c01 = acc[mt][nt][1] + by;
            float c10 = acc[mt][nt][2] + bx, c11 = acc[mt][nt][3] + by;
            if (z < 2) {
                uint32_t* dh = (z == 0) ? g_qh : g_kh;
                uint32_t* dl = (z == 0) ? g_ql : g_kl;
                size_t p0 = (size_t)(bm + row) * 512 + ((bn + col) >> 1);
                size_t p1 = (size_t)(bm + row + 8) * 512 + ((bn + col) >> 1);
                uint32_t h, l;
                split2(c00, c01, h, l);
                dh[p0] = h; dl[p0] = l;
                split2(c10, c11, h, l);
                dh[p1] = h; dl[p1] = l;
            } else {
                *(float2*)(g_v + (size_t)(bm + row) * 1024 + bn + col) = make_float2(c00, c01);
                *(float2*)(g_v + (size_t)(bm + row + 8) * 1024 + bn + col) = make_float2(c10, c11);
            }
        }
    }
}

// ===========================================================================
// V transpose+pack: g_v (natural) -> g_vth/g_vtl [bh][d][cpair].
// ===========================================================================
__global__ __launch_bounds__(256) void vt_kernel()
{
    __shared__ uint32_t sh[64 * 65], sl[64 * 65];
    const int bh = blockIdx.y, ct = blockIdx.x, tid = threadIdx.x;

    #pragma unroll
    for (int s = 0; s < 16; s++) {
        int idx = tid + 256 * s;
        int d = idx & 63, cp = idx >> 6;
        const float* p = g_v + (size_t)(ct * 128 + 2 * cp) * 4096 + bh * 64 + d;
        float x0 = p[0], x1 = p[4096];
        uint32_t h, l;
        split2(x0, x1, h, l);
        sh[cp * 65 + d] = h;
        sl[cp * 65 + d] = l;
    }
    __syncthreads();
    #pragma unroll
    for (int s = 0; s < 16; s++) {
        int idx = tid + 256 * s;
        int cp = idx & 63, d = idx >> 6;
        size_t o = ((size_t)(bh * 64 + d) << 9) + ct * 64 + cp;
        g_vth[o] = sh[cp * 65 + d];
        g_vtl[o] = sl[cp * 65 + d];
    }
}

// ===========================================================================
// Attention: register-resident scores; 4-stage cp.async pipeline,
// single barrier per tile-iteration, prefetch distance 3.
// ===========================================================================
#define KV_W   0                         // K: 4 x 9216 w; V phase: 4 x 8704 w
#define QH_W   36864
#define QL_W   (QH_W + 1152)             // 38016
#define SCRM_W (QL_W + 1152)             // 39168
#define SCRS_W (SCRM_W + 256)            // 39424
#define BIA_W  (SCRS_W + 256)            // 39680; 4 buffers of 32x132
#define ATTN_SMEM_WORDS (BIA_W + 4 * 4224)    // 56576
#define ATTN_SMEM_BYTES (ATTN_SMEM_WORDS * 4) // 226304

__global__ __launch_bounds__(512, 1) void attn_mma_kernel(
    const float* __restrict__ bias, float* __restrict__ out_attn, float* __restrict__ w_out)
{
    extern __shared__ float sm[];
    float* scrM = sm + SCRM_W;
    float* scrS = sm + SCRS_W;
    const uint32_t smb = smem_u32(sm);

    const int tid = threadIdx.x;
    const int w = tid >> 5, lane = tid & 31;
    const int g = lane >> 2, t = lane & 3;
    const int l8 = lane & 7;
    const int wm = w >> 3, wn = w & 7;
    const int m0 = wm * 16, n0 = wn * 16;
    const int bh = blockIdx.y;
    const int r0 = blockIdx.x * 32;

    const float* bsrc = bias + (size_t)(bh & 3) * Nn * Nn;
    float* wbase = (w_out != nullptr) ? w_out : g_w;
    float* wrow_base = wbase + (size_t)bh * Nn * Nn;

    const int qfb = (m0 + ((lane >> 3) & 1) * 8 + l8) * 36 + ((lane >> 4) & 1) * 4;
    const int kfb = (n0 + ((lane >> 4) & 1) * 8 + l8) * 36 + ((lane >> 3) & 1) * 4;
    const int vfb = (((lane >> 4) & 1) * 8 + l8) * 68 + wn * 8 + ((lane >> 3) & 1) * 4;

    // K tile + bias tile in ONE commit group; 4 buffers (b = it & 3)
    auto issueK = [&](int it) {
        int b = it & 3;
        #pragma unroll
        for (int s = 0; s < 4; s++) {
            int idx = tid + 512 * s;
            int plane = idx >> 10;
            int row = (idx >> 3) & 127;
            int seg = idx & 7;
            const uint32_t* src = (plane ? g_kl : g_kh) +
                (size_t)(it * 128 + row) * 2048 + bh * 32 + seg * 4;
            cp16(smb + (uint32_t)(KV_W + b * 9216 + plane * 4608 + row * 36 + seg * 4) * 4, src);
        }
        #pragma unroll
        for (int s = 0; s < 2; s++) {
            int idx = tid + 512 * s;
            int row = idx >> 5;
            int seg = idx & 31;
            const float* src = bsrc + (size_t)(r0 + row) * 1024 + it * 128 + seg * 4;
            cp16(smb + (uint32_t)(BIA_W + b * 4224 + row * 132 + seg * 4) * 4, src);
        }
        cp_commit();
    };
    auto issueV = [&](int it) {
        int b = it & 3;
        #pragma unroll
        for (int s = 0; s < 4; s++) {
            int idx = tid + 512 * s;
            int plane = idx >> 10;
            int row = (idx >> 4) & 63;
            int seg = idx & 15;
            const uint32_t* src = (plane ? g_vtl : g_vth) +
                (((size_t)(bh * 64 + row)) << 9) + it * 64 + seg * 4;
            cp16(smb + (uint32_t)(KV_W + b * 8704 + plane * 4352 + row * 68 + seg * 4) * 4, src);
        }
        cp_commit();
    };

    // ---- prologue: Q, K0..K2 (prefetch depth 3) ----
    {
        int plane = tid >> 8, ci = tid & 255, row = ci >> 3, seg = ci & 7;
        const uint32_t* src = (plane ? g_ql : g_qh) +
            (size_t)(r0 + row) * 2048 + bh * 32 + seg * 4;
        cp16(smb + (uint32_t)((plane ? QL_W : QH_W) + row * 36 + seg * 4) * 4, src);
        cp_commit();
    }
    issueK(0);
    issueK(1);
    issueK(2);

    cp_wait<3>();   // Q done
    __syncthreads();
    uint32_t qah[4][4], qal[4][4];
    #pragma unroll
    for (int ks = 0; ks < 4; ks++) {
        ldsm_x4(qah[ks], smb + (uint32_t)(QH_W + qfb + ks * 8) * 4);
        ldsm_x4(qal[ks], smb + (uint32_t)(QL_W + qfb + ks * 8) * 4);
    }

    // ---- scores into registers (64 floats/thread) ----
    float sv[64];
    #pragma unroll
    for (int j = 0; j < 64; j++) sv[j] = 0.0f;

    const int rowg = r0 + m0 + g;

    #pragma unroll
    for (int it = 0; it < 8; it++) {
        if (it < 6) cp_wait<2>(); else if (it == 6) cp_wait<1>(); else cp_wait<0>();
        __syncthreads();
        if (it + 3 <= 7) issueK(it + 3);   // writes buf (it-1)&3: readers passed bar
        const uint32_t KHa = smb + (uint32_t)((it & 3) * 9216 + kfb) * 4;
        const uint32_t KLa = KHa + 4608 * 4;
        const float* Bb = sm + BIA_W + (it & 3) * 4224;
        float* s = sv + it * 8;

        #pragma unroll
        for (int ks = 0; ks < 4; ks++) {
            uint32_t bhf[4], blf[4];
            ldsm_x4(bhf, KHa + ks * 32);
            ldsm_x4(blf, KLa + ks * 32);
            mma_bf16(s,     qah[ks], bhf);
            mma_bf16(s,     qah[ks], blf);
            mma_bf16(s,     qal[ks], bhf);
            mma_bf16(s + 4, qah[ks], bhf + 2);
            mma_bf16(s + 4, qah[ks], blf + 2);
            mma_bf16(s + 4, qal[ks], bhf + 2);
        }
        {
            int c0l = n0 + 2 * t;
            float2 b00 = *(const float2*)&Bb[(m0 + g) * 132 + c0l];
            float2 b01 = *(const float2*)&Bb[(m0 + g + 8) * 132 + c0l];
            float2 b10 = *(const float2*)&Bb[(m0 + g) * 132 + c0l + 8];
            float2 b11 = *(const float2*)&Bb[(m0 + g + 8) * 132 + c0l + 8];
            s[0] += b00.x; s[1] += b00.y;
            s[2] += b01.x; s[3] += b01.y;
            s[4] += b10.x; s[5] += b10.y;
            s[6] += b11.x; s[7] += b11.y;
        }
    }

    // ---- V pipeline prologue (V0..V2; overlaps softmax). V0..V2 regions
    // (< kbuf3) don't collide with score-it7's kbuf3 reads.
    issueV(0);
    issueV(1);
    issueV(2);

    // ---- softmax: quad shuffle + cross-warp smem reduce ----
    float mg = -3.0e38f, mg8 = -3.0e38f;
    #pragma unroll
    for (int it = 0; it < 8; it++) {
        float* s = sv + it * 8;
        mg  = fmaxf(mg,  fmaxf(fmaxf(s[0], s[1]), fmaxf(s[4], s[5])));
        mg8 = fmaxf(mg8, fmaxf(fmaxf(s[2], s[3]), fmaxf(s[6], s[7])));
    }
    mg  = fmaxf(mg,  __shfl_xor_sync(0xffffffffu, mg, 1));
    mg  = fmaxf(mg,  __shfl_xor_sync(0xffffffffu, mg, 2));
    mg8 = fmaxf(mg8, __shfl_xor_sync(0xffffffffu, mg8, 1));
    mg8 = fmaxf(mg8, __shfl_xor_sync(0xffffffffu, mg8, 2));
    if (t == 0) {
        scrM[(m0 + g) * 8 + wn]     = mg;
        scrM[(m0 + g + 8) * 8 + wn] = mg8;
    }
    __syncthreads();
    float Mg = -3.0e38f, Mg8 = -3.0e38f;
    #pragma unroll
    for (int k = 0; k < 8; k++) {
        Mg  = fmaxf(Mg,  scrM[(m0 + g) * 8 + k]);
        Mg8 = fmaxf(Mg8, scrM[(m0 + g + 8) * 8 + k]);
    }
    float sg = 0.0f, sg8 = 0.0f;
    #pragma unroll
    for (int it = 0; it < 8; it++) {
        float* s = sv + it * 8;
        s[0] = __expf(s[0] - Mg);  s[1] = __expf(s[1] - Mg);
        s[4] = __expf(s[4] - Mg);  s[5] = __expf(s[5] - Mg);
        s[2] = __expf(s[2] - Mg8); s[3] = __expf(s[3] - Mg8);
        s[6] = __expf(s[6] - Mg8); s[7] = __expf(s[7] - Mg8);
        sg  += s[0] + s[1] + s[4] + s[5];
        sg8 += s[2] + s[3] + s[6] + s[7];
    }
    sg  += __shfl_xor_sync(0xffffffffu, sg, 1);
    sg  += __shfl_xor_sync(0xffffffffu, sg, 2);
    sg8 += __shfl_xor_sync(0xffffffffu, sg8, 1);
    sg8 += __shfl_xor_sync(0xffffffffu, sg8, 2);
    if (t == 0) {
        scrS[(m0 + g) * 8 + wn]     = sg;
        scrS[(m0 + g + 8) * 8 + wn] = sg8;
    }
    __syncthreads();
    float Sg = 0.0f, Sg8 = 0.0f;
    #pragma unroll
    for (int k = 0; k < 8; k++) {
        Sg  += scrS[(m0 + g) * 8 + k];
        Sg8 += scrS[(m0 + g + 8) * 8 + k];
    }
    const float invg = 1.0f / Sg, invg8 = 1.0f / Sg8;

    // ---- AV loop: 4-stage, single barrier; per-tile P pack + MMA ----
    float* wr0 = wrow_base + (size_t)rowg * 1024;
    float* wr8 = wrow_base + (size_t)(rowg + 8) * 1024;

    float oacc[8][4];
    #pragma unroll
    for (int i = 0; i < 8; i++)
        #pragma unroll
        for (int j = 0; j < 4; j++) oacc[i][j] = 0.0f;

    #pragma unroll
    for (int it = 0; it < 8; it++) {
        if (it < 6) cp_wait<2>(); else if (it == 6) cp_wait<1>(); else cp_wait<0>();
        __syncthreads();
        if (it + 3 <= 7) issueV(it + 3);
        const uint32_t VHa = smb + (uint32_t)((it & 3) * 8704 + vfb) * 4;
        const uint32_t VLa = VHa + 4352 * 4;

        float* s = sv + it * 8;
        float p0 = s[0] * invg,  p1 = s[1] * invg;
        float p2 = s[2] * invg8, p3 = s[3] * invg8;
        float p4 = s[4] * invg,  p5 = s[5] * invg;
        float p6 = s[6] * invg8, p7 = s[7] * invg8;
        int c0 = it * 128 + n0 + 2 * t;
        *(float2*)&wr0[c0]     = make_float2(p0, p1);
        *(float2*)&wr8[c0]     = make_float2(p2, p3);
        *(float2*)&wr0[c0 + 8] = make_float2(p4, p5);
        *(float2*)&wr8[c0 + 8] = make_float2(p6, p7);
        uint32_t pah[4], pal[4];
        split2(p0, p1, pah[0], pal[0]);
        split2(p2, p3, pah[1], pal[1]);
        split2(p4, p5, pah[2], pal[2]);
        split2(p6, p7, pah[3], pal[3]);

        #pragma unroll
        for (int ntp = 0; ntp < 8; ntp += 2) {
            uint32_t vhf[4], vlf[4];
            ldsm_x4(vhf, VHa + ntp * 2176);
            ldsm_x4(vlf, VLa + ntp * 2176);
            mma_bf16(oacc[ntp],     pah, vhf);
            mma_bf16(oacc[ntp],     pah, vlf);
            mma_bf16(oacc[ntp],     pal, vhf);
            mma_bf16(oacc[ntp + 1], pah, vhf + 2);
            mma_bf16(oacc[ntp + 1], pah, vlf + 2);
            mma_bf16(oacc[ntp + 1], pal, vhf + 2);
        }
    }

    // ---- tree-reduce 8 wn-partials (overlay on KV region) ----
    __syncthreads();
    float* red = sm + KV_W;
    auto stPart = [&](int b) {
        int base = b * 2176 + wm * 1088;
        #pragma unroll
        for (int nt = 0; nt < 8; nt++) {
            *(float2*)&red[base + g * 66 + nt * 8 + 2 * t] =
                make_float2(oacc[nt][0], oacc[nt][1]);
            *(float2*)&red[base + (g + 8) * 66 + nt * 8 + 2 * t] =
                make_float2(oacc[nt][2], oacc[nt][3]);
        }
    };
    auto addPart = [&](int b) {
        int base = b * 2176 + wm * 1088;
        #pragma unroll
        for (int nt = 0; nt < 8; nt++) {
            float2 p0 = *(float2*)&red[base + g * 66 + nt * 8 + 2 * t];
            float2 p1 = *(float2*)&red[base + (g + 8) * 66 + nt * 8 + 2 * t];
            oacc[nt][0] += p0.x; oacc[nt][1] += p0.y;
            oacc[nt][2] += p1.x; oacc[nt][3] += p1.y;
        }
    };
    if (wn >= 4) stPart(wn - 4);
    __syncthreads();
    if (wn < 4) addPart(wn);
    __syncthreads();
    if (wn == 2 || wn == 3) stPart(wn - 2);
    __syncthreads();
    if (wn < 2) addPart(wn);
    __syncthreads();
    if (wn == 1) stPart(0);
    __syncthreads();
    if (wn == 0) {
        addPart(0);
        size_t ob = (size_t)(bh >> 4) * Nn * Ee + (size_t)(bh & 15) * 64;
        #pragma unroll
        for (int nt = 0; nt < 8; nt++) {
            int col = nt * 8 + 2 * t;
            *(float2*)&out_attn[ob + (size_t)rowg * Ee + col] =
                make_float2(oacc[nt][0], oacc[nt][1]);
            *(float2*)&out_attn[ob + (size_t)(rowg + 8) * Ee + col] =
                make_float2(oacc[nt][2], oacc[nt][3]);
        }
    }
}

// ---------------------------------------------------------------------------
extern "C" void kernel_launch(void* const* d_in, const int* in_sizes, int n_in,
                              void* d_out, int out_size) {
    const float* query = (const float*)d_in[0];
    const float* key_  = (const float*)d_in[1];
    const float* value = (const float*)d_in[2];
    const float* ab    = (const float*)d_in[3];
    const float* Wq    = (const float*)d_in[4];
    const float* bq    = (const float*)d_in[5];
    const float* Wk    = (const float*)d_in[6];
    const float* bk    = (const float*)d_in[7];
    const float* Wv    = (const float*)d_in[8];
    const float* bv    = (const float*)d_in[9];

    float* out = (float*)d_out;
    const long long attn_elems = (long long)Bc * Nn * Ee;
    const long long w_elems    = (long long)BHn * Nn * Nn;
    float* attn_out = out;
    float* w_out = nullptr;
    if ((long long)out_size >= attn_elems + w_elems) w_out = out + attn_elems;

    {
        dim3 grid(4096, 6);
        pack_kernel<<<grid, 256>>>(query, key_, value, Wq, Wk, Wv);
    }
    {
        cudaFuncSetAttribute(proj_mma_kernel, cudaFuncAttributeMaxDynamicSharedMemorySize,
                             PROJ_SMEM_BYTES);
        dim3 grid(Mtot / 128, Ee / 128, 3);
        proj_mma_kernel<<<grid, 256, PROJ_SMEM_BYTES>>>(bq, bk, bv);
    }
    {
        dim3 grid(8, 64);
        vt_kernel<<<grid, 256>>>();
    }
    {
        cudaFuncSetAttribute(attn_mma_kernel, cudaFuncAttributeMaxDynamicSharedMemorySize,
                             ATTN_SMEM_BYTES);
        dim3 grid(Nn / 32, BHn);
        attn_mma_kernel<<<grid, 512, ATTN_SMEM_BYTES>>>(ab, attn_out, w_out);
    }
}